// round 10
// baseline (speedup 1.0000x reference)
#include <cuda_runtime.h>
#include <stdint.h>

typedef unsigned long long ull;

// ---------------------------------------------------------------------------
// Scratch (device globals — no allocation allowed)
// ---------------------------------------------------------------------------
__device__ float g_Wall[128 * 384];   // [Uk | Uq | Wv] fp32
__device__ float g_ball[384];         // [ck+ba1 | cq | bv]
__device__ float g_hkq[2048 * 256];   // [hk | hq]
__device__ float g_dots[2048 * 8];    // per row: [kdot h0..h3 (incl ba2) | qdot h0..h3]
__device__ float g_w[8 * 1024 * 1024];// attention weights (tf32-rounded) per (b,h)
__device__ float g_c[2048 * 640];     // [v | o0..o3] fp32
__device__ float g_h1[2048 * 256];    // decoder hidden fp32

// ---------------------------------------------------------------------------
// helpers
// ---------------------------------------------------------------------------
__device__ __forceinline__ ull pack2(float lo, float hi) {
    ull r; asm("mov.b64 %0, {%1, %2};" : "=l"(r) : "f"(lo), "f"(hi)); return r;
}
__device__ __forceinline__ void unpack2(ull v, float& lo, float& hi) {
    asm("mov.b64 {%0, %1}, %2;" : "=f"(lo), "=f"(hi) : "l"(v));
}
__device__ __forceinline__ ull fma2(ull a, ull b, ull c) {
    ull d; asm("fma.rn.f32x2 %0, %1, %2, %3;" : "=l"(d) : "l"(a), "l"(b), "l"(c)); return d;
}
__device__ __forceinline__ ull add2(ull a, ull b) {
    ull d; asm("add.rn.f32x2 %0, %1, %2;" : "=l"(d) : "l"(a), "l"(b)); return d;
}
__device__ __forceinline__ float rna_tf32(float x) {
    uint32_t r; asm("cvt.rna.tf32.f32 %0, %1;" : "=r"(r) : "f"(x));
    return __uint_as_float(r);
}
__device__ __forceinline__ void mma_tf32(float c[4],
    uint32_t a0, uint32_t a1, uint32_t a2, uint32_t a3,
    uint32_t b0, uint32_t b1)
{
    asm("mma.sync.aligned.m16n8k8.row.col.f32.tf32.tf32.f32 "
        "{%0,%1,%2,%3},{%4,%5,%6,%7},{%8,%9},{%0,%1,%2,%3};"
        : "+f"(c[0]), "+f"(c[1]), "+f"(c[2]), "+f"(c[3])
        : "r"(a0), "r"(a1), "r"(a2), "r"(a3), "r"(b0), "r"(b1));
}
__device__ __forceinline__ uint32_t fu(float x) { return __float_as_uint(x); }

// MUFU-free sigmoid (2 Newton iters on d in (1,2], rel err ~1e-5).
__device__ __forceinline__ float sigmoid_fma(float s) {
    float t = s * 1.4426950408889634f;
    float tn = -fabsf(t);
    tn = fmaxf(tn, -125.0f);
    float m = tn + 12582912.0f;
    int ib = __float_as_int(m);
    float n = m - 12582912.0f;
    float f = tn - n;
    float p = 1.33335581e-3f;
    p = fmaf(p, f, 9.61812910e-3f);
    p = fmaf(p, f, 5.55041087e-2f);
    p = fmaf(p, f, 2.40226507e-1f);
    p = fmaf(p, f, 6.93147181e-1f);
    p = fmaf(p, f, 1.0f);
    float scale = __int_as_float((ib - 0x4B400000 + 127) << 23);
    float e = p * scale;
    float d = 1.0f + e;
    float r = fmaf(d, -0.47058824f, 1.41176471f);
    r = r * fmaf(-d, r, 2.0f);
    r = r * fmaf(-d, r, 2.0f);
    float sn = e * r;
    return (s > 0.0f) ? (1.0f - sn) : sn;
}

// ---------------------------------------------------------------------------
// prep: fused [Uk|Uq|Wv] (fp32) + fused bias (ba1 folded into hk bias).
// ---------------------------------------------------------------------------
__global__ __launch_bounds__(256) void prep_kernel(
    const float* __restrict__ Wk, const float* __restrict__ bk,
    const float* __restrict__ Wq, const float* __restrict__ bq,
    const float* __restrict__ Wv, const float* __restrict__ bv,
    const float* __restrict__ Wa1, const float* __restrict__ ba1)
{
    __shared__ float wa[64 * 32];
    int tid = threadIdx.x;
    for (int i = tid; i < 64 * 32; i += 256) wa[i] = Wa1[i];
    __syncthreads();

    int stride = gridDim.x * 256;
    for (int idx = blockIdx.x * 256 + tid; idx < 128 * 128; idx += stride) {
        int d = idx >> 7, j = idx & 127;
        int hb = j & ~31, a = j & 31;
        float sk = 0.f, sq = 0.f;
        #pragma unroll
        for (int t = 0; t < 32; t++) {
            sk += Wk[d * 128 + hb + t] * wa[t * 32 + a];
            sq += Wq[d * 128 + hb + t] * wa[(32 + t) * 32 + a];
        }
        g_Wall[d * 384 + j]       = sk;
        g_Wall[d * 384 + 128 + j] = sq;
        g_Wall[d * 384 + 256 + j] = Wv[d * 128 + j];
    }
    if (blockIdx.x == 0 && tid < 128) {
        int hb = tid & ~31, a = tid & 31;
        float sk = 0.f, sq = 0.f;
        #pragma unroll
        for (int t = 0; t < 32; t++) {
            sk += bk[hb + t] * wa[t * 32 + a];
            sq += bq[hb + t] * wa[(32 + t) * 32 + a];
        }
        g_ball[tid]       = sk + ba1[a];
        g_ball[128 + tid] = sq;
        g_ball[256 + tid] = bv[tid];
    }
}

// ---------------------------------------------------------------------------
// dots: per (row, head): kdot = ba2 + sum_a hk*Wa2/2 ; qdot = sum_a hq*Wa2/2
// ---------------------------------------------------------------------------
__global__ __launch_bounds__(256) void dots_kernel(
    const float* __restrict__ hkq, const float* __restrict__ Wa2,
    const float* __restrict__ ba2)
{
    int idx = blockIdx.x * 256 + threadIdx.x;
    if (idx >= 2048 * 8) return;
    int row = idx >> 3, r = idx & 7;
    int isq = r >> 2, h = r & 3;
    const float* base = hkq + (size_t)row * 256 + isq * 128 + h * 32;
    float s = 0.f;
    #pragma unroll
    for (int a = 0; a < 32; a++) s += base[a] * (0.5f * Wa2[a]);
    if (!isq) s += ba2[0];
    g_dots[idx] = s;
}

// ---------------------------------------------------------------------------
// score: w[bh][i][j] = rna(sigmoid(kdot[i]+qdot[j]+sum_a |hk+hq|*Wa2/2 - mask))
// Block = 64 i x 256 j. grid (4 jt, 16 it, 8 bh) = 512 blocks -> 1 wave @ occ4.
// ---------------------------------------------------------------------------
__global__ __launch_bounds__(256, 4) void score_kernel(
    const float* __restrict__ hkq, const float* __restrict__ dots,
    float* __restrict__ wbuf, const float* __restrict__ Wa2)
{
    __shared__ float hk_s[64 * 36];
    __shared__ float kdot_s[64];
    __shared__ ull wa2s[16];

    int tid = threadIdx.x;
    int jt = blockIdx.x, itile = blockIdx.y, bh = blockIdx.z;
    int b = bh >> 2, h = bh & 3;
    int ibase = itile * 64;
    int jloc = jt * 256 + tid;
    size_t brow = (size_t)b * 1024;

    #pragma unroll
    for (int s = 0; s < 2; s++) {   // hk tile: 64 rows x 32 a = 512 float4
        int lin = tid + s * 256;
        int row = lin >> 3, g = lin & 7;
        float4 f = *(const float4*)(hkq + (brow + ibase + row) * 256 + h * 32 + g * 4);
        *(float4*)&hk_s[row * 36 + g * 4] = f;
    }
    if (tid < 64) kdot_s[tid] = dots[(brow + ibase + tid) * 8 + h];
    if (tid < 16) {
        float a0 = 0.5f * Wa2[2 * tid], a1 = 0.5f * Wa2[2 * tid + 1];
        wa2s[tid] = pack2(a0, a1);
    }

    ull qp[8][2];
    {
        const float* qr = hkq + (brow + jloc) * 256 + 128 + h * 32;
        #pragma unroll
        for (int a4 = 0; a4 < 8; a4++) {
            ulonglong2 u = *(const ulonglong2*)(qr + a4 * 4);
            qp[a4][0] = u.x; qp[a4][1] = u.y;
        }
    }
    float qd = dots[(brow + jloc) * 8 + 4 + h];
    __syncthreads();

    const ull ABSM = 0x7FFFFFFF7FFFFFFFULL;
    float* wcol = wbuf + ((size_t)bh << 20) + jloc;

    #pragma unroll 4
    for (int i = 0; i < 64; i++) {
        ull s0 = 0ULL, s1 = 0ULL;
        #pragma unroll
        for (int a4 = 0; a4 < 8; a4++) {
            ulonglong2 k = *(const ulonglong2*)&hk_s[i * 36 + a4 * 4];  // broadcast
            ulonglong2 wp = *(const ulonglong2*)&wa2s[a4 * 2];          // broadcast
            ull u0 = add2(k.x, qp[a4][0]);
            ull u1 = add2(k.y, qp[a4][1]);
            s0 = fma2(u0 & ABSM, wp.x, s0);
            s1 = fma2(u1 & ABSM, wp.y, s1);
        }
        float f0, f1, f2, f3;
        unpack2(s0, f0, f1);
        unpack2(s1, f2, f3);
        float s = kdot_s[i] + qd + ((f0 + f1) + (f2 + f3));
        if (ibase + i == jloc) s -= 10000.f;
        wcol[(size_t)(ibase + i) * 1024] = rna_tf32(sigmoid_fma(s));
    }
}

// ---------------------------------------------------------------------------
// TF32 GEMM: C = act(A @ W + bias).  128 threads, tile 32x64 (4 warps, each
// m32 x n16 — warp-level code identical to the proven 64x64 version).
// SPLIT: A hi/lo (exact), 2 mma passes; else single pass, A rounded at STS.
// B always rounded at STS.  K-chunk 32, double-buffered, 1 sync/chunk.
// smem (floats): SPLIT: AsH[2][1152] AsL[2][1152] Bs[2][2304] = 36864 B
//                else:  AsH[2][1152] Bs[2][2304]             = 27648 B
// ---------------------------------------------------------------------------
#define GEMM_SMEM_SPLIT 36864
#define GEMM_SMEM_1X    27648

template <bool RELU, bool SPLIT>
__global__ __launch_bounds__(128, SPLIT ? 4 : 6) void gemm_k(
    const float* __restrict__ A, int lda,
    const float* __restrict__ W, int ldw,
    const float* __restrict__ bias,
    float* __restrict__ C1, int ldc1,
    float* __restrict__ C2, int ldc2, int nsplit,
    int K)
{
    extern __shared__ float sm[];
    float* AsH = sm;                            // [2][1152]
    float* AsL = SPLIT ? sm + 2304 : sm;        // [2][1152]
    float* Bs  = sm + (SPLIT ? 4608 : 2304);    // [2][2304]

    int tid = threadIdx.x;
    int lane = tid & 31, wn = tid >> 5;         // 4 warps, warp wn owns n [wn*16,+16)
    int r = lane >> 2, c4 = lane & 3;
    int m0 = blockIdx.y * 32, n0 = blockIdx.x * 64;

    float acc[2][2][4];
    #pragma unroll
    for (int i = 0; i < 2; i++)
        #pragma unroll
        for (int j = 0; j < 2; j++)
            #pragma unroll
            for (int e = 0; e < 4; e++) acc[i][j][e] = 0.f;

    int nch = K >> 5;

    int am[2], ak0[2], bn[4], bk0[4];
    #pragma unroll
    for (int s = 0; s < 2; s++) {
        int lin = tid + s * 128;                // A: 32m x 8 kgroups = 256 slots
        am[s] = lin >> 3;  ak0[s] = lin & 7;
    }
    #pragma unroll
    for (int s = 0; s < 4; s++) {
        int lin = tid + s * 128;                // B: 64n x 8 kgroups = 512 slots
        bn[s] = lin & 63;  bk0[s] = lin >> 6;
    }

    float rA[2][4], rB[4][4];
    auto ldg_chunk = [&](int kc) {
        #pragma unroll
        for (int s = 0; s < 2; s++)
            #pragma unroll
            for (int u = 0; u < 4; u++)
                rA[s][u] = A[(size_t)(m0 + am[s]) * lda + kc + ak0[s] + 8 * u];
        #pragma unroll
        for (int s = 0; s < 4; s++)
            #pragma unroll
            for (int u = 0; u < 4; u++)
                rB[s][u] = W[(size_t)(kc + bk0[s] + 8 * u) * ldw + n0 + bn[s]];
    };
    auto store_chunk = [&](int buf) {
        float* aH = AsH + buf * 1152;
        float* bs = Bs  + buf * 2304;
        #pragma unroll
        for (int s = 0; s < 2; s++) {
            float4 h;
            h.x = rna_tf32(rA[s][0]); h.y = rna_tf32(rA[s][1]);
            h.z = rna_tf32(rA[s][2]); h.w = rna_tf32(rA[s][3]);
            *(float4*)&aH[am[s] * 36 + ak0[s] * 4] = h;
            if (SPLIT) {
                float* aL = AsL + buf * 1152;
                float4 l;
                l.x = rA[s][0] - h.x; l.y = rA[s][1] - h.y;
                l.z = rA[s][2] - h.z; l.w = rA[s][3] - h.w;
                *(float4*)&aL[am[s] * 36 + ak0[s] * 4] = l;
            }
        }
        #pragma unroll
        for (int s = 0; s < 4; s++) {
            float4 bb;
            bb.x = rna_tf32(rB[s][0]); bb.y = rna_tf32(rB[s][1]);
            bb.z = rna_tf32(rB[s][2]); bb.w = rna_tf32(rB[s][3]);
            *(float4*)&bs[bn[s] * 36 + bk0[s] * 4] = bb;
        }
    };

    ldg_chunk(0);
    store_chunk(0);
    __syncthreads();

    for (int ck = 0; ck < nch; ck++) {
        int p = ck & 1;
        if (ck + 1 < nch) ldg_chunk((ck + 1) << 5);

        const float* aHp = AsH + p * 1152;
        const float* aLp = AsL + p * 1152;
        const float* bsp = Bs  + p * 2304;

        float4 bH0[2], bH1[2];
        #pragma unroll
        for (int nt = 0; nt < 2; nt++) {
            int nb = wn * 16 + nt * 8 + r;
            bH0[nt] = *(const float4*)&bsp[nb * 36 + c4 * 4];
            bH1[nt] = *(const float4*)&bsp[nb * 36 + (c4 + 4) * 4];
        }
        #pragma unroll
        for (int mt = 0; mt < 2; mt++) {
            int rb = mt * 16 + r;
            float4 aH[4], aL[4];
            aH[0] = *(const float4*)&aHp[rb * 36 + c4 * 4];
            aH[1] = *(const float4*)&aHp[(rb + 8) * 36 + c4 * 4];
            aH[2] = *(const float4*)&aHp[rb * 36 + (c4 + 4) * 4];
            aH[3] = *(const float4*)&aHp[(rb + 8) * 36 + (c4 + 4) * 4];
            if (SPLIT) {
                aL[0] = *(const float4*)&aLp[rb * 36 + c4 * 4];
                aL[1] = *(const float4*)&aLp[(rb + 8) * 36 + c4 * 4];
                aL[2] = *(const float4*)&aLp[rb * 36 + (c4 + 4) * 4];
                aL[3] = *(const float4*)&aLp[(rb + 8) * 36 + (c4 + 4) * 4];
            }
            #pragma unroll
            for (int kt = 0; kt < 4; kt++) {
                float ah0 = ((const float*)&aH[0])[kt], ah1 = ((const float*)&aH[1])[kt];
                float ah2 = ((const float*)&aH[2])[kt], ah3 = ((const float*)&aH[3])[kt];
                #pragma unroll
                for (int nt = 0; nt < 2; nt++) {
                    float bh0 = ((const float*)&bH0[nt])[kt], bh1 = ((const float*)&bH1[nt])[kt];
                    mma_tf32(acc[mt][nt], fu(ah0), fu(ah1), fu(ah2), fu(ah3), fu(bh0), fu(bh1));
                    if (SPLIT) {
                        float al0 = ((const float*)&aL[0])[kt], al1 = ((const float*)&aL[1])[kt];
                        float al2 = ((const float*)&aL[2])[kt], al3 = ((const float*)&aL[3])[kt];
                        mma_tf32(acc[mt][nt], fu(al0), fu(al1), fu(al2), fu(al3), fu(bh0), fu(bh1));
                    }
                }
            }
        }
        if (ck + 1 < nch) store_chunk(1 - p);
        __syncthreads();
    }

    bool left = (n0 < nsplit);
    float* Cb = left ? (C1 + n0) : (C2 + (n0 - nsplit));
    int ldc = left ? ldc1 : ldc2;

    #pragma unroll
    for (int mt = 0; mt < 2; mt++) {
        #pragma unroll
        for (int nt = 0; nt < 2; nt++) {
            int row = m0 + mt * 16 + r;
            int col = wn * 16 + nt * 8 + 2 * c4;
            float2 bb = *(const float2*)(bias + n0 + col);
            float o0 = acc[mt][nt][0] + bb.x, o1 = acc[mt][nt][1] + bb.y;
            float o2 = acc[mt][nt][2] + bb.x, o3 = acc[mt][nt][3] + bb.y;
            if (RELU) {
                o0 = fmaxf(o0, 0.f); o1 = fmaxf(o1, 0.f);
                o2 = fmaxf(o2, 0.f); o3 = fmaxf(o3, 0.f);
            }
            *(float2*)(Cb + (size_t)row * ldc + col) = make_float2(o0, o1);
            *(float2*)(Cb + (size_t)(row + 8) * ldc + col) = make_float2(o2, o3);
        }
    }
}

// ---------------------------------------------------------------------------
// wv GEMM, batched over (b,h): out[b][:,128+h*128:+128] = w[bh] @ v[b]
// 128-thread 32x64 tile; single-pass (w pre-rounded; v rounded at STS).
// grid (2 n-tiles, 32 m-tiles, 8 bh) = 512 blocks.
// ---------------------------------------------------------------------------
__global__ __launch_bounds__(128, 6) void wv_gemm(
    const float* __restrict__ wbuf, float* __restrict__ cbuf)
{
    extern __shared__ float sm[];
    float* As = sm;                  // [2][1152]
    float* Bs = sm + 2304;           // [2][2304]

    int tid = threadIdx.x;
    int lane = tid & 31, wn = tid >> 5;
    int r = lane >> 2, c4 = lane & 3;
    int m0 = blockIdx.y * 32, n0 = blockIdx.x * 64;
    int bh = blockIdx.z;
    int b = bh >> 2, h = bh & 3;

    const float* A = wbuf + ((size_t)bh << 20);            // lda = 1024
    const float* V = cbuf + (size_t)b * 1024 * 640;        // ldw = 640
    float* C = cbuf + (size_t)b * 1024 * 640 + 128 + h * 128 + n0;

    float acc[2][2][4];
    #pragma unroll
    for (int i = 0; i < 2; i++)
        #pragma unroll
        for (int j = 0; j < 2; j++)
            #pragma unroll
            for (int e = 0; e < 4; e++) acc[i][j][e] = 0.f;

    int am[2], ak0[2], bn[4], bk0[4];
    #pragma unroll
    for (int s = 0; s < 2; s++) {
        int lin = tid + s * 128;
        am[s] = lin >> 3;  ak0[s] = lin & 7;
    }
    #pragma unroll
    for (int s = 0; s < 4; s++) {
        int lin = tid + s * 128;
        bn[s] = lin & 63;  bk0[s] = lin >> 6;
    }

    float rA[2][4], rB[4][4];
    auto ldg_chunk = [&](int kc) {
        #pragma unroll
        for (int s = 0; s < 2; s++)
            #pragma unroll
            for (int u = 0; u < 4; u++)
                rA[s][u] = A[(size_t)(m0 + am[s]) * 1024 + kc + ak0[s] + 8 * u];
        #pragma unroll
        for (int s = 0; s < 4; s++)
            #pragma unroll
            for (int u = 0; u < 4; u++)
                rB[s][u] = V[(size_t)(kc + bk0[s] + 8 * u) * 640 + n0 + bn[s]];
    };
    auto store_chunk = [&](int buf) {
        float* as = As + buf * 1152;
        float* bs = Bs + buf * 2304;
        #pragma unroll
        for (int s = 0; s < 2; s++) {
            float4 a;   // w pre-rounded: direct store
            a.x = rA[s][0]; a.y = rA[s][1]; a.z = rA[s][2]; a.w = rA[s][3];
            *(float4*)&as[am[s] * 36 + ak0[s] * 4] = a;
        }
        #pragma unroll
        for (int s = 0; s < 4; s++) {
            float4 bb;
            bb.x = rna_tf32(rB[s][0]); bb.y = rna_tf32(rB[s][1]);
            bb.z = rna_tf32(rB[s][2]); bb.w = rna_tf32(rB[s][3]);
            *(float4*)&bs[bn[s] * 36 + bk0[s] * 4] = bb;
        }
    };

    ldg_chunk(0);
    store_chunk(0);
    __syncthreads();

    for (int ck = 0; ck < 32; ck++) {
        int p = ck & 1;
        if (ck + 1 < 32) ldg_chunk((ck + 1) << 5);

        const float* asp = As + p * 1152;
        const float* bsp = Bs + p * 2304;

        float4 bH0[2], bH1[2];
        #pragma unroll
        for (int nt = 0; nt < 2; nt++) {
            int nb = wn * 16 + nt * 8 + r;
            bH0[nt] = *(const float4*)&bsp[nb * 36 + c4 * 4];
            bH1[nt] = *(const float4*)&bsp[nb * 36 + (c4 + 4) * 4];
        }
        #pragma unroll
        for (int mt = 0; mt < 2; mt++) {
            int rb = mt * 16 + r;
            float4 aH[4];
            aH[0] = *(const float4*)&asp[rb * 36 + c4 * 4];
            aH[1] = *(const float4*)&asp[(rb + 8) * 36 + c4 * 4];
            aH[2] = *(const float4*)&asp[rb * 36 + (c4 + 4) * 4];
            aH[3] = *(const float4*)&asp[(rb + 8) * 36 + (c4 + 4) * 4];
            #pragma unroll
            for (int kt = 0; kt < 4; kt++) {
                float ah0 = ((const float*)&aH[0])[kt], ah1 = ((const float*)&aH[1])[kt];
                float ah2 = ((const float*)&aH[2])[kt], ah3 = ((const float*)&aH[3])[kt];
                #pragma unroll
                for (int nt = 0; nt < 2; nt++) {
                    float bh0 = ((const float*)&bH0[nt])[kt], bh1 = ((const float*)&bH1[nt])[kt];
                    mma_tf32(acc[mt][nt], fu(ah0), fu(ah1), fu(ah2), fu(ah3), fu(bh0), fu(bh1));
                }
            }
        }
        if (ck + 1 < 32) store_chunk(1 - p);
        __syncthreads();
    }

    #pragma unroll
    for (int mt = 0; mt < 2; mt++) {
        #pragma unroll
        for (int nt = 0; nt < 2; nt++) {
            int row = m0 + mt * 16 + r;
            int col = wn * 16 + nt * 8 + 2 * c4;
            *(float2*)(C + (size_t)row * 640 + col) =
                make_float2(acc[mt][nt][0], acc[mt][nt][1]);
            *(float2*)(C + (size_t)(row + 8) * 640 + col) =
                make_float2(acc[mt][nt][2], acc[mt][nt][3]);
        }
    }
}

// ---------------------------------------------------------------------------
// launch
// ---------------------------------------------------------------------------
extern "C" void kernel_launch(void* const* d_in, const int* in_sizes, int n_in,
                              void* d_out, int out_size)
{
    const float* x   = (const float*)d_in[0];
    const float* Wk  = (const float*)d_in[1];
    const float* bk  = (const float*)d_in[2];
    const float* Wq  = (const float*)d_in[3];
    const float* bq  = (const float*)d_in[4];
    const float* Wv  = (const float*)d_in[5];
    const float* bv  = (const float*)d_in[6];
    const float* Wa1 = (const float*)d_in[7];
    const float* ba1 = (const float*)d_in[8];
    const float* Wa2 = (const float*)d_in[9];
    const float* ba2 = (const float*)d_in[10];
    const float* Wd1 = (const float*)d_in[11];
    const float* bd1 = (const float*)d_in[12];
    const float* Wd2 = (const float*)d_in[13];
    const float* bd2 = (const float*)d_in[14];
    float* out = (float*)d_out;

    float *pWall, *pball, *phkq, *pdots, *pw, *pc, *ph1;
    cudaGetSymbolAddress((void**)&pWall, g_Wall);
    cudaGetSymbolAddress((void**)&pball, g_ball);
    cudaGetSymbolAddress((void**)&phkq, g_hkq);
    cudaGetSymbolAddress((void**)&pdots, g_dots);
    cudaGetSymbolAddress((void**)&pw,   g_w);
    cudaGetSymbolAddress((void**)&pc,   g_c);
    cudaGetSymbolAddress((void**)&ph1,  g_h1);

    // 1. fused effective weights + biases
    prep_kernel<<<16, 256>>>(Wk, bk, Wq, bq, Wv, bv, Wa1, ba1);

    // 2. [hk|hq|v] = x @ Wall + ball   (2-pass: exact A)  grid 6x64 = 384
    gemm_k<false, true><<<dim3(6, 64), 128, GEMM_SMEM_SPLIT>>>(
        x, 128, pWall, 384, pball, phkq, 256, pc, 640, 256, 128);

    // 3. per-(row,head) score dots
    dots_kernel<<<64, 256>>>(phkq, Wa2, ba2);

    // 4. attention scores -> g_w (tf32-rounded)  512 blocks, 1 wave
    score_kernel<<<dim3(4, 16, 8), 256>>>(phkq, pdots, pw, Wa2);

    // 5. o = w @ v  -> g_c cols [128,640)   512 blocks
    wv_gemm<<<dim3(2, 32, 8), 128, GEMM_SMEM_1X>>>(pw, pc);

    // 6. h1 = relu(c @ Wd1 + bd1)   single-pass, 256 blocks
    gemm_k<true, false><<<dim3(4, 64), 128, GEMM_SMEM_1X>>>(
        pc, 640, Wd1, 256, bd1, ph1, 256, ph1, 256, 1 << 30, 640);

    // 7. out = h1 @ Wd2 + bd2       single-pass, 128 blocks
    gemm_k<false, false><<<dim3(2, 64), 128, GEMM_SMEM_1X>>>(
        ph1, 256, Wd2, 128, bd2, out, 128, out, 128, 1 << 30, 256);
}

// round 11
// speedup vs baseline: 1.1314x; 1.1314x over previous
#include <cuda_runtime.h>
#include <stdint.h>

typedef unsigned long long ull;

// ---------------------------------------------------------------------------
// Scratch (device globals — no allocation allowed)
// ---------------------------------------------------------------------------
__device__ float g_Wall[128 * 384];   // [Uk | Uq | Wv] fp32
__device__ float g_ball[384];         // [ck+ba1 | cq | bv]
__device__ float g_hkq[2048 * 256];   // [hk | hq]
__device__ float g_w[8 * 1024 * 1024];// attention weights (tf32-rounded) per (b,h)
__device__ float g_c[2048 * 640];     // [v | o0..o3] fp32
__device__ float g_h1[2048 * 256];    // decoder hidden fp32

// ---------------------------------------------------------------------------
// helpers
// ---------------------------------------------------------------------------
__device__ __forceinline__ ull pack2(float lo, float hi) {
    ull r; asm("mov.b64 %0, {%1, %2};" : "=l"(r) : "f"(lo), "f"(hi)); return r;
}
__device__ __forceinline__ void unpack2(ull v, float& lo, float& hi) {
    asm("mov.b64 {%0, %1}, %2;" : "=f"(lo), "=f"(hi) : "l"(v));
}
__device__ __forceinline__ ull fma2(ull a, ull b, ull c) {
    ull d; asm("fma.rn.f32x2 %0, %1, %2, %3;" : "=l"(d) : "l"(a), "l"(b), "l"(c)); return d;
}
__device__ __forceinline__ ull add2(ull a, ull b) {
    ull d; asm("add.rn.f32x2 %0, %1, %2;" : "=l"(d) : "l"(a), "l"(b)); return d;
}
__device__ __forceinline__ float rna_tf32(float x) {
    uint32_t r; asm("cvt.rna.tf32.f32 %0, %1;" : "=r"(r) : "f"(x));
    return __uint_as_float(r);
}
__device__ __forceinline__ void mma_tf32(float c[4],
    uint32_t a0, uint32_t a1, uint32_t a2, uint32_t a3,
    uint32_t b0, uint32_t b1)
{
    asm("mma.sync.aligned.m16n8k8.row.col.f32.tf32.tf32.f32 "
        "{%0,%1,%2,%3},{%4,%5,%6,%7},{%8,%9},{%0,%1,%2,%3};"
        : "+f"(c[0]), "+f"(c[1]), "+f"(c[2]), "+f"(c[3])
        : "r"(a0), "r"(a1), "r"(a2), "r"(a3), "r"(b0), "r"(b1));
}
__device__ __forceinline__ uint32_t fu(float x) { return __float_as_uint(x); }

// MUFU-free sigmoid (2 Newton iters on d in (1,2], rel err ~1e-5).
__device__ __forceinline__ float sigmoid_fma(float s) {
    float t = s * 1.4426950408889634f;
    float tn = -fabsf(t);
    tn = fmaxf(tn, -125.0f);
    float m = tn + 12582912.0f;
    int ib = __float_as_int(m);
    float n = m - 12582912.0f;
    float f = tn - n;
    float p = 1.33335581e-3f;
    p = fmaf(p, f, 9.61812910e-3f);
    p = fmaf(p, f, 5.55041087e-2f);
    p = fmaf(p, f, 2.40226507e-1f);
    p = fmaf(p, f, 6.93147181e-1f);
    p = fmaf(p, f, 1.0f);
    float scale = __int_as_float((ib - 0x4B400000 + 127) << 23);
    float e = p * scale;
    float d = 1.0f + e;
    float r = fmaf(d, -0.47058824f, 1.41176471f);
    r = r * fmaf(-d, r, 2.0f);
    r = r * fmaf(-d, r, 2.0f);
    float sn = e * r;
    return (s > 0.0f) ? (1.0f - sn) : sn;
}

// ---------------------------------------------------------------------------
// prep: fused [Uk|Uq|Wv] (fp32) + fused bias (ba1 folded into hk bias).
// ---------------------------------------------------------------------------
__global__ __launch_bounds__(256) void prep_kernel(
    const float* __restrict__ Wk, const float* __restrict__ bk,
    const float* __restrict__ Wq, const float* __restrict__ bq,
    const float* __restrict__ Wv, const float* __restrict__ bv,
    const float* __restrict__ Wa1, const float* __restrict__ ba1)
{
    __shared__ float wa[64 * 32];
    int tid = threadIdx.x;
    for (int i = tid; i < 64 * 32; i += 256) wa[i] = Wa1[i];
    __syncthreads();

    int stride = gridDim.x * 256;
    for (int idx = blockIdx.x * 256 + tid; idx < 128 * 128; idx += stride) {
        int d = idx >> 7, j = idx & 127;
        int hb = j & ~31, a = j & 31;
        float sk = 0.f, sq = 0.f;
        #pragma unroll
        for (int t = 0; t < 32; t++) {
            sk += Wk[d * 128 + hb + t] * wa[t * 32 + a];
            sq += Wq[d * 128 + hb + t] * wa[(32 + t) * 32 + a];
        }
        g_Wall[d * 384 + j]       = sk;
        g_Wall[d * 384 + 128 + j] = sq;
        g_Wall[d * 384 + 256 + j] = Wv[d * 128 + j];
    }
    if (blockIdx.x == 0 && tid < 128) {
        int hb = tid & ~31, a = tid & 31;
        float sk = 0.f, sq = 0.f;
        #pragma unroll
        for (int t = 0; t < 32; t++) {
            sk += bk[hb + t] * wa[t * 32 + a];
            sq += bq[hb + t] * wa[(32 + t) * 32 + a];
        }
        g_ball[tid]       = sk + ba1[a];
        g_ball[128 + tid] = sq;
        g_ball[256 + tid] = bv[tid];
    }
}

// ---------------------------------------------------------------------------
// score (with fused dots):
//   kdot[i] = ba2 + sum_a hk[i,a]*Wa2[a]/2   (32 threads, from smem hk tile)
//   qdot    = sum_a hq[j,a]*Wa2[a]/2          (per thread, from q registers)
//   w[bh][i][j] = rna(sigmoid(kdot[i]+qdot+sum_a |hk+hq|*Wa2/2 - mask))
// Block = 32 i x 256 j.  grid (4 jt, 32 it, 8 bh) = 1024 blocks (R9 geometry).
// ---------------------------------------------------------------------------
__global__ __launch_bounds__(256, 4) void score_kernel(
    const float* __restrict__ hkq,
    float* __restrict__ wbuf,
    const float* __restrict__ Wa2,
    const float* __restrict__ ba2)
{
    __shared__ float hk_s[32 * 36];
    __shared__ float kdot_s[32];
    __shared__ ull wa2s[16];

    int tid = threadIdx.x;
    int lane = tid & 31, w = tid >> 5;
    int jt = blockIdx.x, itile = blockIdx.y, bh = blockIdx.z;
    int b = bh >> 2, h = bh & 3;
    int ibase = itile * 32;
    int jloc = jt * 256 + w * 32 + lane;
    size_t brow = (size_t)b * 1024;

    {   // hk tile: 32 rows x 32 a
        int row = tid >> 3, g = tid & 7;
        float4 f = *(const float4*)(hkq + (brow + ibase + row) * 256 + h * 32 + g * 4);
        *(float4*)&hk_s[row * 36 + g * 4] = f;
    }
    if (tid < 16) {
        float a0 = 0.5f * Wa2[2 * tid], a1 = 0.5f * Wa2[2 * tid + 1];
        wa2s[tid] = pack2(a0, a1);
    }

    ull qp[8][2];
    {
        const float* qr = hkq + (brow + jloc) * 256 + 128 + h * 32;
        #pragma unroll
        for (int a4 = 0; a4 < 8; a4++) {
            ulonglong2 u = *(const ulonglong2*)(qr + a4 * 4);
            qp[a4][0] = u.x; qp[a4][1] = u.y;
        }
    }
    float ba2v = ba2[0];
    __syncthreads();

    // fused dots: kdot (threads 0-31, from smem) — includes ba2
    if (tid < 32) {
        float kd = ba2v;
        #pragma unroll
        for (int a4 = 0; a4 < 8; a4++) {
            float lo, hi;
            ulonglong2 wp = *(const ulonglong2*)&wa2s[a4 * 2];
            float w0, w1, w2, w3;
            unpack2(wp.x, w0, w1);
            unpack2(wp.y, w2, w3);
            kd += hk_s[tid * 36 + a4 * 4 + 0] * w0;
            kd += hk_s[tid * 36 + a4 * 4 + 1] * w1;
            kd += hk_s[tid * 36 + a4 * 4 + 2] * w2;
            kd += hk_s[tid * 36 + a4 * 4 + 3] * w3;
            (void)lo; (void)hi;
        }
        kdot_s[tid] = kd;
    }
    // qdot (every thread, from registers + smem wa2)
    float qd;
    {
        ull qacc = 0ULL;
        #pragma unroll
        for (int a4 = 0; a4 < 8; a4++) {
            ulonglong2 wp = *(const ulonglong2*)&wa2s[a4 * 2];
            qacc = fma2(qp[a4][0], wp.x, qacc);
            qacc = fma2(qp[a4][1], wp.y, qacc);
        }
        float q0, q1;
        unpack2(qacc, q0, q1);
        qd = q0 + q1;
    }
    __syncthreads();

    const ull ABSM = 0x7FFFFFFF7FFFFFFFULL;
    float* wcol = wbuf + ((size_t)bh << 20) + jloc;

    #pragma unroll 4
    for (int i = 0; i < 32; i++) {
        ull s0 = 0ULL, s1 = 0ULL;
        #pragma unroll
        for (int a4 = 0; a4 < 8; a4++) {
            ulonglong2 k = *(const ulonglong2*)&hk_s[i * 36 + a4 * 4];  // broadcast
            ulonglong2 wp = *(const ulonglong2*)&wa2s[a4 * 2];          // broadcast
            ull u0 = add2(k.x, qp[a4][0]);
            ull u1 = add2(k.y, qp[a4][1]);
            s0 = fma2(u0 & ABSM, wp.x, s0);
            s1 = fma2(u1 & ABSM, wp.y, s1);
        }
        float f0, f1, f2, f3;
        unpack2(s0, f0, f1);
        unpack2(s1, f2, f3);
        float s = kdot_s[i] + qd + ((f0 + f1) + (f2 + f3));
        if (ibase + i == jloc) s -= 10000.f;
        wcol[(size_t)(ibase + i) * 1024] = rna_tf32(sigmoid_fma(s));
    }
}

// ---------------------------------------------------------------------------
// TF32 GEMM (R9-proven): 256 threads, tile 64x64, 8 warps (2m x 4n).
// SPLIT: A hi/lo (exact), 2 mma passes; else single pass, A rounded at STS.
// B always rounded at STS.  K-chunk 32, double-buffered, 1 sync/chunk.
// smem: SPLIT: AsH[2][2304]|AsL[2][2304]|Bs[2][2304]=55296 B; else 36864 B.
// ---------------------------------------------------------------------------
#define GEMM_SMEM_SPLIT 55296
#define GEMM_SMEM_1X    36864

template <bool RELU, bool SPLIT>
__global__ __launch_bounds__(256, SPLIT ? 2 : 3) void gemm_k(
    const float* __restrict__ A, int lda,
    const float* __restrict__ W, int ldw,
    const float* __restrict__ bias,
    float* __restrict__ C1, int ldc1,
    float* __restrict__ C2, int ldc2, int nsplit,
    int K)
{
    extern __shared__ float sm[];
    float* AsH = sm;
    float* AsL = SPLIT ? sm + 4608 : sm;
    float* Bs  = sm + (SPLIT ? 9216 : 4608);

    int tid = threadIdx.x;
    int lane = tid & 31, wq = tid >> 5;
    int wm = wq >> 2, wn = wq & 3;
    int r = lane >> 2, c4 = lane & 3;
    int m0 = blockIdx.y * 64, n0 = blockIdx.x * 64;

    float acc[2][2][4];
    #pragma unroll
    for (int i = 0; i < 2; i++)
        #pragma unroll
        for (int j = 0; j < 2; j++)
            #pragma unroll
            for (int e = 0; e < 4; e++) acc[i][j][e] = 0.f;

    int nch = K >> 5;

    int am[2], ak0[2], bn[2], bk0[2];
    #pragma unroll
    for (int s = 0; s < 2; s++) {
        int lin = tid + s * 256;
        am[s] = lin >> 3;  ak0[s] = lin & 7;
        bn[s] = lin & 63;  bk0[s] = lin >> 6;
    }

    float rA[2][4], rB[2][4];
    auto ldg_chunk = [&](int kc) {
        #pragma unroll
        for (int s = 0; s < 2; s++)
            #pragma unroll
            for (int u = 0; u < 4; u++) {
                rA[s][u] = A[(size_t)(m0 + am[s]) * lda + kc + ak0[s] + 8 * u];
                rB[s][u] = W[(size_t)(kc + bk0[s] + 8 * u) * ldw + n0 + bn[s]];
            }
    };
    auto store_chunk = [&](int buf) {
        float* aH = AsH + buf * 2304;
        float* bs = Bs  + buf * 2304;
        #pragma unroll
        for (int s = 0; s < 2; s++) {
            float4 h;
            h.x = rna_tf32(rA[s][0]); h.y = rna_tf32(rA[s][1]);
            h.z = rna_tf32(rA[s][2]); h.w = rna_tf32(rA[s][3]);
            *(float4*)&aH[am[s] * 36 + ak0[s] * 4] = h;
            if (SPLIT) {
                float* aL = AsL + buf * 2304;
                float4 l;
                l.x = rA[s][0] - h.x; l.y = rA[s][1] - h.y;
                l.z = rA[s][2] - h.z; l.w = rA[s][3] - h.w;
                *(float4*)&aL[am[s] * 36 + ak0[s] * 4] = l;
            }
            float4 b;
            b.x = rna_tf32(rB[s][0]); b.y = rna_tf32(rB[s][1]);
            b.z = rna_tf32(rB[s][2]); b.w = rna_tf32(rB[s][3]);
            *(float4*)&bs[bn[s] * 36 + bk0[s] * 4] = b;
        }
    };

    ldg_chunk(0);
    store_chunk(0);
    __syncthreads();

    for (int ck = 0; ck < nch; ck++) {
        int p = ck & 1;
        if (ck + 1 < nch) ldg_chunk((ck + 1) << 5);

        const float* aHp = AsH + p * 2304;
        const float* aLp = AsL + p * 2304;
        const float* bsp = Bs  + p * 2304;

        float4 bH0[2], bH1[2];
        #pragma unroll
        for (int nt = 0; nt < 2; nt++) {
            int nb = wn * 16 + nt * 8 + r;
            bH0[nt] = *(const float4*)&bsp[nb * 36 + c4 * 4];
            bH1[nt] = *(const float4*)&bsp[nb * 36 + (c4 + 4) * 4];
        }
        #pragma unroll
        for (int mt = 0; mt < 2; mt++) {
            int rb = wm * 32 + mt * 16 + r;
            float4 aH[4], aL[4];
            aH[0] = *(const float4*)&aHp[rb * 36 + c4 * 4];
            aH[1] = *(const float4*)&aHp[(rb + 8) * 36 + c4 * 4];
            aH[2] = *(const float4*)&aHp[rb * 36 + (c4 + 4) * 4];
            aH[3] = *(const float4*)&aHp[(rb + 8) * 36 + (c4 + 4) * 4];
            if (SPLIT) {
                aL[0] = *(const float4*)&aLp[rb * 36 + c4 * 4];
                aL[1] = *(const float4*)&aLp[(rb + 8) * 36 + c4 * 4];
                aL[2] = *(const float4*)&aLp[rb * 36 + (c4 + 4) * 4];
                aL[3] = *(const float4*)&aLp[(rb + 8) * 36 + (c4 + 4) * 4];
            }
            #pragma unroll
            for (int kt = 0; kt < 4; kt++) {
                float ah0 = ((const float*)&aH[0])[kt], ah1 = ((const float*)&aH[1])[kt];
                float ah2 = ((const float*)&aH[2])[kt], ah3 = ((const float*)&aH[3])[kt];
                #pragma unroll
                for (int nt = 0; nt < 2; nt++) {
                    float bh0 = ((const float*)&bH0[nt])[kt], bh1 = ((const float*)&bH1[nt])[kt];
                    mma_tf32(acc[mt][nt], fu(ah0), fu(ah1), fu(ah2), fu(ah3), fu(bh0), fu(bh1));
                    if (SPLIT) {
                        float al0 = ((const float*)&aL[0])[kt], al1 = ((const float*)&aL[1])[kt];
                        float al2 = ((const float*)&aL[2])[kt], al3 = ((const float*)&aL[3])[kt];
                        mma_tf32(acc[mt][nt], fu(al0), fu(al1), fu(al2), fu(al3), fu(bh0), fu(bh1));
                    }
                }
            }
        }
        if (ck + 1 < nch) store_chunk(1 - p);
        __syncthreads();
    }

    bool left = (n0 < nsplit);
    float* Cb = left ? (C1 + n0) : (C2 + (n0 - nsplit));
    int ldc = left ? ldc1 : ldc2;

    #pragma unroll
    for (int mt = 0; mt < 2; mt++) {
        #pragma unroll
        for (int nt = 0; nt < 2; nt++) {
            int row = m0 + wm * 32 + mt * 16 + r;
            int col = wn * 16 + nt * 8 + 2 * c4;
            float2 bb = *(const float2*)(bias + n0 + col);
            float o0 = acc[mt][nt][0] + bb.x, o1 = acc[mt][nt][1] + bb.y;
            float o2 = acc[mt][nt][2] + bb.x, o3 = acc[mt][nt][3] + bb.y;
            if (RELU) {
                o0 = fmaxf(o0, 0.f); o1 = fmaxf(o1, 0.f);
                o2 = fmaxf(o2, 0.f); o3 = fmaxf(o3, 0.f);
            }
            *(float2*)(Cb + (size_t)row * ldc + col) = make_float2(o0, o1);
            *(float2*)(Cb + (size_t)(row + 8) * ldc + col) = make_float2(o2, o3);
        }
    }
}

// ---------------------------------------------------------------------------
// wv GEMM, batched over (b,h): out[b][:,128+h*128:+128] = w[bh] @ v[b]
// R9-proven: 256 threads, 64x64 tile; single-pass (w pre-rounded; v rounded).
// grid (2 n-tiles, 16 m-tiles, 8 bh) = 256 blocks.
// ---------------------------------------------------------------------------
__global__ __launch_bounds__(256, 3) void wv_gemm(
    const float* __restrict__ wbuf, float* __restrict__ cbuf)
{
    extern __shared__ float sm[];
    float* As = sm;
    float* Bs = sm + 4608;

    int tid = threadIdx.x;
    int lane = tid & 31, wq = tid >> 5;
    int wm = wq >> 2, wn = wq & 3;
    int r = lane >> 2, c4 = lane & 3;
    int m0 = blockIdx.y * 64, n0 = blockIdx.x * 64;
    int bh = blockIdx.z;
    int b = bh >> 2, h = bh & 3;

    const float* A = wbuf + ((size_t)bh << 20);            // lda = 1024
    const float* V = cbuf + (size_t)b * 1024 * 640;        // ldw = 640
    float* C = cbuf + (size_t)b * 1024 * 640 + 128 + h * 128 + n0;

    float acc[2][2][4];
    #pragma unroll
    for (int i = 0; i < 2; i++)
        #pragma unroll
        for (int j = 0; j < 2; j++)
            #pragma unroll
            for (int e = 0; e < 4; e++) acc[i][j][e] = 0.f;

    int am[2], ak0[2], bn[2], bk0[2];
    #pragma unroll
    for (int s = 0; s < 2; s++) {
        int lin = tid + s * 256;
        am[s] = lin >> 3;  ak0[s] = lin & 7;
        bn[s] = lin & 63;  bk0[s] = lin >> 6;
    }

    float rA[2][4], rB[2][4];
    auto ldg_chunk = [&](int kc) {
        #pragma unroll
        for (int s = 0; s < 2; s++)
            #pragma unroll
            for (int u = 0; u < 4; u++) {
                rA[s][u] = A[(size_t)(m0 + am[s]) * 1024 + kc + ak0[s] + 8 * u];
                rB[s][u] = V[(size_t)(kc + bk0[s] + 8 * u) * 640 + n0 + bn[s]];
            }
    };
    auto store_chunk = [&](int buf) {
        float* as = As + buf * 2304;
        float* bs = Bs + buf * 2304;
        #pragma unroll
        for (int s = 0; s < 2; s++) {
            float4 a;   // w pre-rounded: direct store
            a.x = rA[s][0]; a.y = rA[s][1]; a.z = rA[s][2]; a.w = rA[s][3];
            *(float4*)&as[am[s] * 36 + ak0[s] * 4] = a;
            float4 bb;
            bb.x = rna_tf32(rB[s][0]); bb.y = rna_tf32(rB[s][1]);
            bb.z = rna_tf32(rB[s][2]); bb.w = rna_tf32(rB[s][3]);
            *(float4*)&bs[bn[s] * 36 + bk0[s] * 4] = bb;
        }
    };

    ldg_chunk(0);
    store_chunk(0);
    __syncthreads();

    for (int ck = 0; ck < 32; ck++) {
        int p = ck & 1;
        if (ck + 1 < 32) ldg_chunk((ck + 1) << 5);

        const float* asp = As + p * 2304;
        const float* bsp = Bs + p * 2304;

        float4 bH0[2], bH1[2];
        #pragma unroll
        for (int nt = 0; nt < 2; nt++) {
            int nb = wn * 16 + nt * 8 + r;
            bH0[nt] = *(const float4*)&bsp[nb * 36 + c4 * 4];
            bH1[nt] = *(const float4*)&bsp[nb * 36 + (c4 + 4) * 4];
        }
        #pragma unroll
        for (int mt = 0; mt < 2; mt++) {
            int rb = wm * 32 + mt * 16 + r;
            float4 aH[4];
            aH[0] = *(const float4*)&asp[rb * 36 + c4 * 4];
            aH[1] = *(const float4*)&asp[(rb + 8) * 36 + c4 * 4];
            aH[2] = *(const float4*)&asp[rb * 36 + (c4 + 4) * 4];
            aH[3] = *(const float4*)&asp[(rb + 8) * 36 + (c4 + 4) * 4];
            #pragma unroll
            for (int kt = 0; kt < 4; kt++) {
                float ah0 = ((const float*)&aH[0])[kt], ah1 = ((const float*)&aH[1])[kt];
                float ah2 = ((const float*)&aH[2])[kt], ah3 = ((const float*)&aH[3])[kt];
                #pragma unroll
                for (int nt = 0; nt < 2; nt++) {
                    float bh0 = ((const float*)&bH0[nt])[kt], bh1 = ((const float*)&bH1[nt])[kt];
                    mma_tf32(acc[mt][nt], fu(ah0), fu(ah1), fu(ah2), fu(ah3), fu(bh0), fu(bh1));
                }
            }
        }
        if (ck + 1 < 32) store_chunk(1 - p);
        __syncthreads();
    }

    #pragma unroll
    for (int mt = 0; mt < 2; mt++) {
        #pragma unroll
        for (int nt = 0; nt < 2; nt++) {
            int row = m0 + wm * 32 + mt * 16 + r;
            int col = wn * 16 + nt * 8 + 2 * c4;
            *(float2*)(C + (size_t)row * 640 + col) =
                make_float2(acc[mt][nt][0], acc[mt][nt][1]);
            *(float2*)(C + (size_t)(row + 8) * 640 + col) =
                make_float2(acc[mt][nt][2], acc[mt][nt][3]);
        }
    }
}

// ---------------------------------------------------------------------------
// launch
// ---------------------------------------------------------------------------
extern "C" void kernel_launch(void* const* d_in, const int* in_sizes, int n_in,
                              void* d_out, int out_size)
{
    const float* x   = (const float*)d_in[0];
    const float* Wk  = (const float*)d_in[1];
    const float* bk  = (const float*)d_in[2];
    const float* Wq  = (const float*)d_in[3];
    const float* bq  = (const float*)d_in[4];
    const float* Wv  = (const float*)d_in[5];
    const float* bv  = (const float*)d_in[6];
    const float* Wa1 = (const float*)d_in[7];
    const float* ba1 = (const float*)d_in[8];
    const float* Wa2 = (const float*)d_in[9];
    const float* ba2 = (const float*)d_in[10];
    const float* Wd1 = (const float*)d_in[11];
    const float* bd1 = (const float*)d_in[12];
    const float* Wd2 = (const float*)d_in[13];
    const float* bd2 = (const float*)d_in[14];
    float* out = (float*)d_out;

    float *pWall, *pball, *phkq, *pw, *pc, *ph1;
    cudaGetSymbolAddress((void**)&pWall, g_Wall);
    cudaGetSymbolAddress((void**)&pball, g_ball);
    cudaGetSymbolAddress((void**)&phkq, g_hkq);
    cudaGetSymbolAddress((void**)&pw,   g_w);
    cudaGetSymbolAddress((void**)&pc,   g_c);
    cudaGetSymbolAddress((void**)&ph1,  g_h1);

    cudaFuncSetAttribute((const void*)gemm_k<false, true>,
                         cudaFuncAttributeMaxDynamicSharedMemorySize, GEMM_SMEM_SPLIT);
    cudaFuncSetAttribute((const void*)gemm_k<true, false>,
                         cudaFuncAttributeMaxDynamicSharedMemorySize, GEMM_SMEM_1X);
    cudaFuncSetAttribute((const void*)gemm_k<false, false>,
                         cudaFuncAttributeMaxDynamicSharedMemorySize, GEMM_SMEM_1X);
    cudaFuncSetAttribute((const void*)wv_gemm,
                         cudaFuncAttributeMaxDynamicSharedMemorySize, GEMM_SMEM_1X);

    // 1. fused effective weights + biases
    prep_kernel<<<32, 256>>>(Wk, bk, Wq, bq, Wv, bv, Wa1, ba1);

    // 2. [hk|hq|v] = x @ Wall + ball   (2-pass: exact A)  grid 192
    gemm_k<false, true><<<dim3(6, 32), 256, GEMM_SMEM_SPLIT>>>(
        x, 128, pWall, 384, pball, phkq, 256, pc, 640, 256, 128);

    // 3. attention scores (dots fused) -> g_w (tf32-rounded)  1024 blocks
    score_kernel<<<dim3(4, 32, 8), 256>>>(phkq, pw, Wa2, ba2);

    // 4. o = w @ v  -> g_c cols [128,640)   256 blocks, single-pass
    wv_gemm<<<dim3(2, 16, 8), 256, GEMM_SMEM_1X>>>(pw, pc);

    // 5. h1 = relu(c @ Wd1 + bd1)   single-pass, 128 blocks
    gemm_k<true, false><<<dim3(4, 32), 256, GEMM_SMEM_1X>>>(
        pc, 640, Wd1, 256, bd1, ph1, 256, ph1, 256, 1 << 30, 640);

    // 6. out = h1 @ Wd2 + bd2       single-pass, 64 blocks
    gemm_k<false, false><<<dim3(2, 32), 256, GEMM_SMEM_1X>>>(
        ph1, 256, Wd2, 128, bd2, out, 128, out, 128, 1 << 30, 256);
}

// round 12
// speedup vs baseline: 1.1474x; 1.0141x over previous
#include <cuda_runtime.h>
#include <stdint.h>

typedef unsigned long long ull;

// ---------------------------------------------------------------------------
// Scratch (device globals — no allocation allowed)
// ---------------------------------------------------------------------------
__device__ float g_Wall[128 * 384];    // [Uk | Uq | Wv] fp32
__device__ float g_ball[384];          // [ck+ba1 | cq | bv]
__device__ float g_hkq[2048 * 256];    // [hk | hq]
__device__ float g_w[8 * 1024 * 1024]; // attention weights (tf32-rounded)
__device__ float g_c[2048 * 640];      // [v | o0..o3] fp32
__device__ float g_h1[2048 * 256];     // decoder hidden fp32
__device__ float g_part[4 * 8 * 1024 * 128];  // wv split-K partials
__device__ float g_pd[2 * 2048 * 256];        // dec split-K partials (reused)

// ---------------------------------------------------------------------------
// helpers
// ---------------------------------------------------------------------------
__device__ __forceinline__ ull pack2(float lo, float hi) {
    ull r; asm("mov.b64 %0, {%1, %2};" : "=l"(r) : "f"(lo), "f"(hi)); return r;
}
__device__ __forceinline__ void unpack2(ull v, float& lo, float& hi) {
    asm("mov.b64 {%0, %1}, %2;" : "=f"(lo), "=f"(hi) : "l"(v));
}
__device__ __forceinline__ ull fma2(ull a, ull b, ull c) {
    ull d; asm("fma.rn.f32x2 %0, %1, %2, %3;" : "=l"(d) : "l"(a), "l"(b), "l"(c)); return d;
}
__device__ __forceinline__ ull add2(ull a, ull b) {
    ull d; asm("add.rn.f32x2 %0, %1, %2;" : "=l"(d) : "l"(a), "l"(b)); return d;
}
__device__ __forceinline__ float rna_tf32(float x) {
    uint32_t r; asm("cvt.rna.tf32.f32 %0, %1;" : "=r"(r) : "f"(x));
    return __uint_as_float(r);
}
__device__ __forceinline__ void mma_tf32(float c[4],
    uint32_t a0, uint32_t a1, uint32_t a2, uint32_t a3,
    uint32_t b0, uint32_t b1)
{
    asm("mma.sync.aligned.m16n8k8.row.col.f32.tf32.tf32.f32 "
        "{%0,%1,%2,%3},{%4,%5,%6,%7},{%8,%9},{%0,%1,%2,%3};"
        : "+f"(c[0]), "+f"(c[1]), "+f"(c[2]), "+f"(c[3])
        : "r"(a0), "r"(a1), "r"(a2), "r"(a3), "r"(b0), "r"(b1));
}
__device__ __forceinline__ uint32_t fu(float x) { return __float_as_uint(x); }

// MUFU-free sigmoid (2 Newton iters on d in (1,2], rel err ~1e-5).
__device__ __forceinline__ float sigmoid_fma(float s) {
    float t = s * 1.4426950408889634f;
    float tn = -fabsf(t);
    tn = fmaxf(tn, -125.0f);
    float m = tn + 12582912.0f;
    int ib = __float_as_int(m);
    float n = m - 12582912.0f;
    float f = tn - n;
    float p = 1.33335581e-3f;
    p = fmaf(p, f, 9.61812910e-3f);
    p = fmaf(p, f, 5.55041087e-2f);
    p = fmaf(p, f, 2.40226507e-1f);
    p = fmaf(p, f, 6.93147181e-1f);
    p = fmaf(p, f, 1.0f);
    float scale = __int_as_float((ib - 0x4B400000 + 127) << 23);
    float e = p * scale;
    float d = 1.0f + e;
    float r = fmaf(d, -0.47058824f, 1.41176471f);
    r = r * fmaf(-d, r, 2.0f);
    r = r * fmaf(-d, r, 2.0f);
    float sn = e * r;
    return (s > 0.0f) ? (1.0f - sn) : sn;
}

// ---------------------------------------------------------------------------
// prep: fused [Uk|Uq|Wv] (fp32) + fused bias (ba1 folded into hk bias).
// ---------------------------------------------------------------------------
__global__ __launch_bounds__(256) void prep_kernel(
    const float* __restrict__ Wk, const float* __restrict__ bk,
    const float* __restrict__ Wq, const float* __restrict__ bq,
    const float* __restrict__ Wv, const float* __restrict__ bv,
    const float* __restrict__ Wa1, const float* __restrict__ ba1)
{
    __shared__ float wa[64 * 32];
    int tid = threadIdx.x;
    for (int i = tid; i < 64 * 32; i += 256) wa[i] = Wa1[i];
    __syncthreads();

    int stride = gridDim.x * 256;
    for (int idx = blockIdx.x * 256 + tid; idx < 128 * 128; idx += stride) {
        int d = idx >> 7, j = idx & 127;
        int hb = j & ~31, a = j & 31;
        float sk = 0.f, sq = 0.f;
        #pragma unroll
        for (int t = 0; t < 32; t++) {
            sk += Wk[d * 128 + hb + t] * wa[t * 32 + a];
            sq += Wq[d * 128 + hb + t] * wa[(32 + t) * 32 + a];
        }
        g_Wall[d * 384 + j]       = sk;
        g_Wall[d * 384 + 128 + j] = sq;
        g_Wall[d * 384 + 256 + j] = Wv[d * 128 + j];
    }
    if (blockIdx.x == 0 && tid < 128) {
        int hb = tid & ~31, a = tid & 31;
        float sk = 0.f, sq = 0.f;
        #pragma unroll
        for (int t = 0; t < 32; t++) {
            sk += bk[hb + t] * wa[t * 32 + a];
            sq += bq[hb + t] * wa[(32 + t) * 32 + a];
        }
        g_ball[tid]       = sk + ba1[a];
        g_ball[128 + tid] = sq;
        g_ball[256 + tid] = bv[tid];
    }
}

// ---------------------------------------------------------------------------
// score (dots fused): w[bh][i][j] = rna(sigmoid(kdot[i]+qdot[j]+Σ|hk+hq|·Wa2/2 - mask))
// Block = 32 i x 256 j. grid (4 jt, 32 it, 8 bh) = 1024 blocks.
// ---------------------------------------------------------------------------
__global__ __launch_bounds__(256, 4) void score_kernel(
    const float* __restrict__ hkq,
    float* __restrict__ wbuf,
    const float* __restrict__ Wa2,
    const float* __restrict__ ba2)
{
    __shared__ float hk_s[32 * 36];
    __shared__ float kdot_s[32];
    __shared__ ull wa2s[16];

    int tid = threadIdx.x;
    int lane = tid & 31, w = tid >> 5;
    int jt = blockIdx.x, itile = blockIdx.y, bh = blockIdx.z;
    int b = bh >> 2, h = bh & 3;
    int ibase = itile * 32;
    int jloc = jt * 256 + w * 32 + lane;
    size_t brow = (size_t)b * 1024;

    {   // hk tile: 32 rows x 32 a
        int row = tid >> 3, g = tid & 7;
        float4 f = *(const float4*)(hkq + (brow + ibase + row) * 256 + h * 32 + g * 4);
        *(float4*)&hk_s[row * 36 + g * 4] = f;
    }
    if (tid < 16) {
        float a0 = 0.5f * Wa2[2 * tid], a1 = 0.5f * Wa2[2 * tid + 1];
        wa2s[tid] = pack2(a0, a1);
    }

    ull qp[8][2];
    {
        const float* qr = hkq + (brow + jloc) * 256 + 128 + h * 32;
        #pragma unroll
        for (int a4 = 0; a4 < 8; a4++) {
            ulonglong2 u = *(const ulonglong2*)(qr + a4 * 4);
            qp[a4][0] = u.x; qp[a4][1] = u.y;
        }
    }
    float ba2v = ba2[0];
    __syncthreads();

    if (tid < 32) {
        float kd = ba2v;
        #pragma unroll
        for (int a4 = 0; a4 < 8; a4++) {
            ulonglong2 wp = *(const ulonglong2*)&wa2s[a4 * 2];
            float w0, w1, w2, w3;
            unpack2(wp.x, w0, w1);
            unpack2(wp.y, w2, w3);
            kd += hk_s[tid * 36 + a4 * 4 + 0] * w0;
            kd += hk_s[tid * 36 + a4 * 4 + 1] * w1;
            kd += hk_s[tid * 36 + a4 * 4 + 2] * w2;
            kd += hk_s[tid * 36 + a4 * 4 + 3] * w3;
        }
        kdot_s[tid] = kd;
    }
    float qd;
    {
        ull qacc = 0ULL;
        #pragma unroll
        for (int a4 = 0; a4 < 8; a4++) {
            ulonglong2 wp = *(const ulonglong2*)&wa2s[a4 * 2];
            qacc = fma2(qp[a4][0], wp.x, qacc);
            qacc = fma2(qp[a4][1], wp.y, qacc);
        }
        float q0, q1;
        unpack2(qacc, q0, q1);
        qd = q0 + q1;
    }
    __syncthreads();

    const ull ABSM = 0x7FFFFFFF7FFFFFFFULL;
    float* wcol = wbuf + ((size_t)bh << 20) + jloc;

    #pragma unroll 4
    for (int i = 0; i < 32; i++) {
        ull s0 = 0ULL, s1 = 0ULL;
        #pragma unroll
        for (int a4 = 0; a4 < 8; a4++) {
            ulonglong2 k = *(const ulonglong2*)&hk_s[i * 36 + a4 * 4];
            ulonglong2 wp = *(const ulonglong2*)&wa2s[a4 * 2];
            ull u0 = add2(k.x, qp[a4][0]);
            ull u1 = add2(k.y, qp[a4][1]);
            s0 = fma2(u0 & ABSM, wp.x, s0);
            s1 = fma2(u1 & ABSM, wp.y, s1);
        }
        float f0, f1, f2, f3;
        unpack2(s0, f0, f1);
        unpack2(s1, f2, f3);
        float s = kdot_s[i] + qd + ((f0 + f1) + (f2 + f3));
        if (ibase + i == jloc) s -= 10000.f;
        wcol[(size_t)(ibase + i) * 1024] = rna_tf32(sigmoid_fma(s));
    }
}

// ---------------------------------------------------------------------------
// qkv GEMM (2-pass, exact A): 256 threads, 64x64 tile, double-buffered.
// ---------------------------------------------------------------------------
#define GEMM_SMEM_SPLIT 55296
#define GEMM_SMEM_1X    36864

__global__ __launch_bounds__(256, 2) void gemm_qkv(
    const float* __restrict__ A, int lda,
    const float* __restrict__ W, int ldw,
    const float* __restrict__ bias,
    float* __restrict__ C1, int ldc1,
    float* __restrict__ C2, int ldc2, int nsplit,
    int K)
{
    extern __shared__ float sm[];
    float* AsH = sm;
    float* AsL = sm + 4608;
    float* Bs  = sm + 9216;

    int tid = threadIdx.x;
    int lane = tid & 31, wq = tid >> 5;
    int wm = wq >> 2, wn = wq & 3;
    int r = lane >> 2, c4 = lane & 3;
    int m0 = blockIdx.y * 64, n0 = blockIdx.x * 64;

    float acc[2][2][4];
    #pragma unroll
    for (int i = 0; i < 2; i++)
        #pragma unroll
        for (int j = 0; j < 2; j++)
            #pragma unroll
            for (int e = 0; e < 4; e++) acc[i][j][e] = 0.f;

    int nch = K >> 5;

    int am[2], ak0[2], bn[2], bk0[2];
    #pragma unroll
    for (int s = 0; s < 2; s++) {
        int lin = tid + s * 256;
        am[s] = lin >> 3;  ak0[s] = lin & 7;
        bn[s] = lin & 63;  bk0[s] = lin >> 6;
    }

    float rA[2][4], rB[2][4];
    auto ldg_chunk = [&](int kc) {
        #pragma unroll
        for (int s = 0; s < 2; s++)
            #pragma unroll
            for (int u = 0; u < 4; u++) {
                rA[s][u] = A[(size_t)(m0 + am[s]) * lda + kc + ak0[s] + 8 * u];
                rB[s][u] = W[(size_t)(kc + bk0[s] + 8 * u) * ldw + n0 + bn[s]];
            }
    };
    auto store_chunk = [&](int buf) {
        float* aH = AsH + buf * 2304;
        float* aL = AsL + buf * 2304;
        float* bs = Bs  + buf * 2304;
        #pragma unroll
        for (int s = 0; s < 2; s++) {
            float4 h, l;
            h.x = rna_tf32(rA[s][0]); h.y = rna_tf32(rA[s][1]);
            h.z = rna_tf32(rA[s][2]); h.w = rna_tf32(rA[s][3]);
            l.x = rA[s][0] - h.x; l.y = rA[s][1] - h.y;
            l.z = rA[s][2] - h.z; l.w = rA[s][3] - h.w;
            *(float4*)&aH[am[s] * 36 + ak0[s] * 4] = h;
            *(float4*)&aL[am[s] * 36 + ak0[s] * 4] = l;
            float4 b;
            b.x = rna_tf32(rB[s][0]); b.y = rna_tf32(rB[s][1]);
            b.z = rna_tf32(rB[s][2]); b.w = rna_tf32(rB[s][3]);
            *(float4*)&bs[bn[s] * 36 + bk0[s] * 4] = b;
        }
    };

    ldg_chunk(0);
    store_chunk(0);
    __syncthreads();

    for (int ck = 0; ck < nch; ck++) {
        int p = ck & 1;
        if (ck + 1 < nch) ldg_chunk((ck + 1) << 5);

        const float* aHp = AsH + p * 2304;
        const float* aLp = AsL + p * 2304;
        const float* bsp = Bs  + p * 2304;

        float4 bH0[2], bH1[2];
        #pragma unroll
        for (int nt = 0; nt < 2; nt++) {
            int nb = wn * 16 + nt * 8 + r;
            bH0[nt] = *(const float4*)&bsp[nb * 36 + c4 * 4];
            bH1[nt] = *(const float4*)&bsp[nb * 36 + (c4 + 4) * 4];
        }
        #pragma unroll
        for (int mt = 0; mt < 2; mt++) {
            int rb = wm * 32 + mt * 16 + r;
            float4 aH[4], aL[4];
            aH[0] = *(const float4*)&aHp[rb * 36 + c4 * 4];
            aH[1] = *(const float4*)&aHp[(rb + 8) * 36 + c4 * 4];
            aH[2] = *(const float4*)&aHp[rb * 36 + (c4 + 4) * 4];
            aH[3] = *(const float4*)&aHp[(rb + 8) * 36 + (c4 + 4) * 4];
            aL[0] = *(const float4*)&aLp[rb * 36 + c4 * 4];
            aL[1] = *(const float4*)&aLp[(rb + 8) * 36 + c4 * 4];
            aL[2] = *(const float4*)&aLp[rb * 36 + (c4 + 4) * 4];
            aL[3] = *(const float4*)&aLp[(rb + 8) * 36 + (c4 + 4) * 4];
            #pragma unroll
            for (int kt = 0; kt < 4; kt++) {
                float ah0 = ((const float*)&aH[0])[kt], ah1 = ((const float*)&aH[1])[kt];
                float ah2 = ((const float*)&aH[2])[kt], ah3 = ((const float*)&aH[3])[kt];
                float al0 = ((const float*)&aL[0])[kt], al1 = ((const float*)&aL[1])[kt];
                float al2 = ((const float*)&aL[2])[kt], al3 = ((const float*)&aL[3])[kt];
                #pragma unroll
                for (int nt = 0; nt < 2; nt++) {
                    float bh0 = ((const float*)&bH0[nt])[kt], bh1 = ((const float*)&bH1[nt])[kt];
                    mma_tf32(acc[mt][nt], fu(ah0), fu(ah1), fu(ah2), fu(ah3), fu(bh0), fu(bh1));
                    mma_tf32(acc[mt][nt], fu(al0), fu(al1), fu(al2), fu(al3), fu(bh0), fu(bh1));
                }
            }
        }
        if (ck + 1 < nch) store_chunk(1 - p);
        __syncthreads();
    }

    bool left = (n0 < nsplit);
    float* Cb = left ? (C1 + n0) : (C2 + (n0 - nsplit));
    int ldc = left ? ldc1 : ldc2;

    #pragma unroll
    for (int mt = 0; mt < 2; mt++) {
        #pragma unroll
        for (int nt = 0; nt < 2; nt++) {
            int row = m0 + wm * 32 + mt * 16 + r;
            int col = wn * 16 + nt * 8 + 2 * c4;
            float2 bb = *(const float2*)(bias + n0 + col);
            float o0 = acc[mt][nt][0] + bb.x, o1 = acc[mt][nt][1] + bb.y;
            float o2 = acc[mt][nt][2] + bb.x, o3 = acc[mt][nt][3] + bb.y;
            *(float2*)(Cb + (size_t)row * ldc + col) = make_float2(o0, o1);
            *(float2*)(Cb + (size_t)(row + 8) * ldc + col) = make_float2(o2, o3);
        }
    }
}

// ---------------------------------------------------------------------------
// wv GEMM, split-K=4, batched over (b,h).  grid (2 n, 16 m, 32 z) where
// z = bh*4 + sp.  Each block: 64x64 tile over k in [sp*256, +256) (8 chunks).
// Partials -> g_part[z][1024x128].  Single-pass tf32 (w pre-rounded).
// ---------------------------------------------------------------------------
__global__ __launch_bounds__(256, 3) void wv_gemm(
    const float* __restrict__ wbuf, const float* __restrict__ cbuf,
    float* __restrict__ part)
{
    extern __shared__ float sm[];
    float* As = sm;
    float* Bs = sm + 4608;

    int tid = threadIdx.x;
    int lane = tid & 31, wq = tid >> 5;
    int wm = wq >> 2, wn = wq & 3;
    int r = lane >> 2, c4 = lane & 3;
    int m0 = blockIdx.y * 64, n0 = blockIdx.x * 64;
    int z = blockIdx.z;
    int bh = z >> 2, sp = z & 3;
    int b = bh >> 2;
    int kbase = sp << 8;

    const float* A = wbuf + ((size_t)bh << 20);            // lda = 1024
    const float* V = cbuf + (size_t)b * 1024 * 640;        // ldw = 640
    float* P = part + (size_t)z * 131072 + n0;             // ldc = 128

    float acc[2][2][4];
    #pragma unroll
    for (int i = 0; i < 2; i++)
        #pragma unroll
        for (int j = 0; j < 2; j++)
            #pragma unroll
            for (int e = 0; e < 4; e++) acc[i][j][e] = 0.f;

    int am[2], ak0[2], bn[2], bk0[2];
    #pragma unroll
    for (int s = 0; s < 2; s++) {
        int lin = tid + s * 256;
        am[s] = lin >> 3;  ak0[s] = lin & 7;
        bn[s] = lin & 63;  bk0[s] = lin >> 6;
    }

    float rA[2][4], rB[2][4];
    auto ldg_chunk = [&](int kc) {
        #pragma unroll
        for (int s = 0; s < 2; s++)
            #pragma unroll
            for (int u = 0; u < 4; u++) {
                rA[s][u] = A[(size_t)(m0 + am[s]) * 1024 + kc + ak0[s] + 8 * u];
                rB[s][u] = V[(size_t)(kc + bk0[s] + 8 * u) * 640 + n0 + bn[s]];
            }
    };
    auto store_chunk = [&](int buf) {
        float* as = As + buf * 2304;
        float* bs = Bs + buf * 2304;
        #pragma unroll
        for (int s = 0; s < 2; s++) {
            float4 a;
            a.x = rA[s][0]; a.y = rA[s][1]; a.z = rA[s][2]; a.w = rA[s][3];
            *(float4*)&as[am[s] * 36 + ak0[s] * 4] = a;
            float4 bb;
            bb.x = rna_tf32(rB[s][0]); bb.y = rna_tf32(rB[s][1]);
            bb.z = rna_tf32(rB[s][2]); bb.w = rna_tf32(rB[s][3]);
            *(float4*)&bs[bn[s] * 36 + bk0[s] * 4] = bb;
        }
    };

    ldg_chunk(kbase);
    store_chunk(0);
    __syncthreads();

    for (int ck = 0; ck < 8; ck++) {
        int p = ck & 1;
        if (ck + 1 < 8) ldg_chunk(kbase + ((ck + 1) << 5));

        const float* asp = As + p * 2304;
        const float* bsp = Bs + p * 2304;

        float4 bH0[2], bH1[2];
        #pragma unroll
        for (int nt = 0; nt < 2; nt++) {
            int nb = wn * 16 + nt * 8 + r;
            bH0[nt] = *(const float4*)&bsp[nb * 36 + c4 * 4];
            bH1[nt] = *(const float4*)&bsp[nb * 36 + (c4 + 4) * 4];
        }
        #pragma unroll
        for (int mt = 0; mt < 2; mt++) {
            int rb = wm * 32 + mt * 16 + r;
            float4 aH[4];
            aH[0] = *(const float4*)&asp[rb * 36 + c4 * 4];
            aH[1] = *(const float4*)&asp[(rb + 8) * 36 + c4 * 4];
            aH[2] = *(const float4*)&asp[rb * 36 + (c4 + 4) * 4];
            aH[3] = *(const float4*)&asp[(rb + 8) * 36 + (c4 + 4) * 4];
            #pragma unroll
            for (int kt = 0; kt < 4; kt++) {
                float ah0 = ((const float*)&aH[0])[kt], ah1 = ((const float*)&aH[1])[kt];
                float ah2 = ((const float*)&aH[2])[kt], ah3 = ((const float*)&aH[3])[kt];
                #pragma unroll
                for (int nt = 0; nt < 2; nt++) {
                    float bh0 = ((const float*)&bH0[nt])[kt], bh1 = ((const float*)&bH1[nt])[kt];
                    mma_tf32(acc[mt][nt], fu(ah0), fu(ah1), fu(ah2), fu(ah3), fu(bh0), fu(bh1));
                }
            }
        }
        if (ck + 1 < 8) store_chunk(1 - p);
        __syncthreads();
    }

    #pragma unroll
    for (int mt = 0; mt < 2; mt++) {
        #pragma unroll
        for (int nt = 0; nt < 2; nt++) {
            int row = m0 + wm * 32 + mt * 16 + r;
            int col = wn * 16 + nt * 8 + 2 * c4;
            *(float2*)(P + (size_t)row * 128 + col) =
                make_float2(acc[mt][nt][0], acc[mt][nt][1]);
            *(float2*)(P + (size_t)(row + 8) * 128 + col) =
                make_float2(acc[mt][nt][2], acc[mt][nt][3]);
        }
    }
}

// wv reduce: sum 4 partials -> g_c cols [128,640).  262144 float4 elements.
__global__ __launch_bounds__(256) void wv_reduce(
    const float* __restrict__ part, float* __restrict__ cbuf)
{
    int i = blockIdx.x * 256 + threadIdx.x;   // f4 index
    if (i >= 8 * 1024 * 32) return;
    int bh = i >> 15;
    int rem = i & 32767;
    int row = rem >> 5, c4 = rem & 31;
    size_t base = ((size_t)bh * 4) * 131072 + row * 128 + c4 * 4;
    float4 s0 = *(const float4*)(part + base);
    float4 s1 = *(const float4*)(part + base + 131072);
    float4 s2 = *(const float4*)(part + base + 2 * 131072);
    float4 s3 = *(const float4*)(part + base + 3 * 131072);
    float4 o;
    o.x = (s0.x + s1.x) + (s2.x + s3.x);
    o.y = (s0.y + s1.y) + (s2.y + s3.y);
    o.z = (s0.z + s1.z) + (s2.z + s3.z);
    o.w = (s0.w + s1.w) + (s2.w + s3.w);
    int b = bh >> 2, h = bh & 3;
    *(float4*)(cbuf + (size_t)(b * 1024 + row) * 640 + 128 + h * 128 + c4 * 4) = o;
}

// ---------------------------------------------------------------------------
// gemm_part: split-K partial GEMM (single-pass tf32; A,B rounded at STS).
// grid (N/64, M/64, nsplit); z picks k range [z*Kper, +Kper).  No bias/act.
// ---------------------------------------------------------------------------
__global__ __launch_bounds__(256, 3) void gemm_part(
    const float* __restrict__ A, int lda,
    const float* __restrict__ W, int ldw,
    float* __restrict__ P, int N, int Kper, int partStride)
{
    extern __shared__ float sm[];
    float* As = sm;
    float* Bs = sm + 4608;

    int tid = threadIdx.x;
    int lane = tid & 31, wq = tid >> 5;
    int wm = wq >> 2, wn = wq & 3;
    int r = lane >> 2, c4 = lane & 3;
    int m0 = blockIdx.y * 64, n0 = blockIdx.x * 64;
    int kbase = blockIdx.z * Kper;
    float* Pz = P + (size_t)blockIdx.z * partStride + n0;

    float acc[2][2][4];
    #pragma unroll
    for (int i = 0; i < 2; i++)
        #pragma unroll
        for (int j = 0; j < 2; j++)
            #pragma unroll
            for (int e = 0; e < 4; e++) acc[i][j][e] = 0.f;

    int nch = Kper >> 5;

    int am[2], ak0[2], bn[2], bk0[2];
    #pragma unroll
    for (int s = 0; s < 2; s++) {
        int lin = tid + s * 256;
        am[s] = lin >> 3;  ak0[s] = lin & 7;
        bn[s] = lin & 63;  bk0[s] = lin >> 6;
    }

    float rA[2][4], rB[2][4];
    auto ldg_chunk = [&](int kc) {
        #pragma unroll
        for (int s = 0; s < 2; s++)
            #pragma unroll
            for (int u = 0; u < 4; u++) {
                rA[s][u] = A[(size_t)(m0 + am[s]) * lda + kc + ak0[s] + 8 * u];
                rB[s][u] = W[(size_t)(kc + bk0[s] + 8 * u) * ldw + n0 + bn[s]];
            }
    };
    auto store_chunk = [&](int buf) {
        float* as = As + buf * 2304;
        float* bs = Bs + buf * 2304;
        #pragma unroll
        for (int s = 0; s < 2; s++) {
            float4 a;
            a.x = rna_tf32(rA[s][0]); a.y = rna_tf32(rA[s][1]);
            a.z = rna_tf32(rA[s][2]); a.w = rna_tf32(rA[s][3]);
            *(float4*)&as[am[s] * 36 + ak0[s] * 4] = a;
            float4 bb;
            bb.x = rna_tf32(rB[s][0]); bb.y = rna_tf32(rB[s][1]);
            bb.z = rna_tf32(rB[s][2]); bb.w = rna_tf32(rB[s][3]);
            *(float4*)&bs[bn[s] * 36 + bk0[s] * 4] = bb;
        }
    };

    ldg_chunk(kbase);
    store_chunk(0);
    __syncthreads();

    for (int ck = 0; ck < nch; ck++) {
        int p = ck & 1;
        if (ck + 1 < nch) ldg_chunk(kbase + ((ck + 1) << 5));

        const float* asp = As + p * 2304;
        const float* bsp = Bs + p * 2304;

        float4 bH0[2], bH1[2];
        #pragma unroll
        for (int nt = 0; nt < 2; nt++) {
            int nb = wn * 16 + nt * 8 + r;
            bH0[nt] = *(const float4*)&bsp[nb * 36 + c4 * 4];
            bH1[nt] = *(const float4*)&bsp[nb * 36 + (c4 + 4) * 4];
        }
        #pragma unroll
        for (int mt = 0; mt < 2; mt++) {
            int rb = wm * 32 + mt * 16 + r;
            float4 aH[4];
            aH[0] = *(const float4*)&asp[rb * 36 + c4 * 4];
            aH[1] = *(const float4*)&asp[(rb + 8) * 36 + c4 * 4];
            aH[2] = *(const float4*)&asp[rb * 36 + (c4 + 4) * 4];
            aH[3] = *(const float4*)&asp[(rb + 8) * 36 + (c4 + 4) * 4];
            #pragma unroll
            for (int kt = 0; kt < 4; kt++) {
                float ah0 = ((const float*)&aH[0])[kt], ah1 = ((const float*)&aH[1])[kt];
                float ah2 = ((const float*)&aH[2])[kt], ah3 = ((const float*)&aH[3])[kt];
                #pragma unroll
                for (int nt = 0; nt < 2; nt++) {
                    float bh0 = ((const float*)&bH0[nt])[kt], bh1 = ((const float*)&bH1[nt])[kt];
                    mma_tf32(acc[mt][nt], fu(ah0), fu(ah1), fu(ah2), fu(ah3), fu(bh0), fu(bh1));
                }
            }
        }
        if (ck + 1 < nch) store_chunk(1 - p);
        __syncthreads();
    }

    #pragma unroll
    for (int mt = 0; mt < 2; mt++) {
        #pragma unroll
        for (int nt = 0; nt < 2; nt++) {
            int row = m0 + wm * 32 + mt * 16 + r;
            int col = wn * 16 + nt * 8 + 2 * c4;
            *(float2*)(Pz + (size_t)row * N + col) =
                make_float2(acc[mt][nt][0], acc[mt][nt][1]);
            *(float2*)(Pz + (size_t)(row + 8) * N + col) =
                make_float2(acc[mt][nt][2], acc[mt][nt][3]);
        }
    }
}

// red2: dst = act(p0 + p1 + bias), float4-vectorized.
template <bool RELU>
__global__ __launch_bounds__(256) void red2(
    const float* __restrict__ p, int partStride,
    const float* __restrict__ bias,
    float* __restrict__ dst, int ncols, int total4)
{
    int i = blockIdx.x * 256 + threadIdx.x;
    if (i >= total4) return;
    float4 a = *(const float4*)(p + (size_t)i * 4);
    float4 b = *(const float4*)(p + partStride + (size_t)i * 4);
    int col = (i * 4) & (ncols - 1);
    float4 bb = *(const float4*)(bias + col);
    float4 o;
    o.x = a.x + b.x + bb.x;
    o.y = a.y + b.y + bb.y;
    o.z = a.z + b.z + bb.z;
    o.w = a.w + b.w + bb.w;
    if (RELU) {
        o.x = fmaxf(o.x, 0.f); o.y = fmaxf(o.y, 0.f);
        o.z = fmaxf(o.z, 0.f); o.w = fmaxf(o.w, 0.f);
    }
    *(float4*)(dst + (size_t)i * 4) = o;
}

// ---------------------------------------------------------------------------
// launch
// ---------------------------------------------------------------------------
extern "C" void kernel_launch(void* const* d_in, const int* in_sizes, int n_in,
                              void* d_out, int out_size)
{
    const float* x   = (const float*)d_in[0];
    const float* Wk  = (const float*)d_in[1];
    const float* bk  = (const float*)d_in[2];
    const float* Wq  = (const float*)d_in[3];
    const float* bq  = (const float*)d_in[4];
    const float* Wv  = (const float*)d_in[5];
    const float* bv  = (const float*)d_in[6];
    const float* Wa1 = (const float*)d_in[7];
    const float* ba1 = (const float*)d_in[8];
    const float* Wa2 = (const float*)d_in[9];
    const float* ba2 = (const float*)d_in[10];
    const float* Wd1 = (const float*)d_in[11];
    const float* bd1 = (const float*)d_in[12];
    const float* Wd2 = (const float*)d_in[13];
    const float* bd2 = (const float*)d_in[14];
    float* out = (float*)d_out;

    float *pWall, *pball, *phkq, *pw, *pc, *ph1, *ppart, *ppd;
    cudaGetSymbolAddress((void**)&pWall, g_Wall);
    cudaGetSymbolAddress((void**)&pball, g_ball);
    cudaGetSymbolAddress((void**)&phkq, g_hkq);
    cudaGetSymbolAddress((void**)&pw,   g_w);
    cudaGetSymbolAddress((void**)&pc,   g_c);
    cudaGetSymbolAddress((void**)&ph1,  g_h1);
    cudaGetSymbolAddress((void**)&ppart, g_part);
    cudaGetSymbolAddress((void**)&ppd,  g_pd);

    cudaFuncSetAttribute((const void*)gemm_qkv,
                         cudaFuncAttributeMaxDynamicSharedMemorySize, GEMM_SMEM_SPLIT);
    cudaFuncSetAttribute((const void*)wv_gemm,
                         cudaFuncAttributeMaxDynamicSharedMemorySize, GEMM_SMEM_1X);
    cudaFuncSetAttribute((const void*)gemm_part,
                         cudaFuncAttributeMaxDynamicSharedMemorySize, GEMM_SMEM_1X);

    // 1. fused effective weights + biases
    prep_kernel<<<32, 256>>>(Wk, bk, Wq, bq, Wv, bv, Wa1, ba1);

    // 2. [hk|hq|v] = x @ Wall + ball   (2-pass: exact A)
    gemm_qkv<<<dim3(6, 32), 256, GEMM_SMEM_SPLIT>>>(
        x, 128, pWall, 384, pball, phkq, 256, pc, 640, 256, 128);

    // 3. attention scores (dots fused) -> g_w (tf32-rounded)
    score_kernel<<<dim3(4, 32, 8), 256>>>(phkq, pw, Wa2, ba2);

    // 4. o = w @ v, split-K=4 -> partials, then reduce into g_c cols [128,640)
    wv_gemm<<<dim3(2, 16, 32), 256, GEMM_SMEM_1X>>>(pw, pc, ppart);
    wv_reduce<<<1024, 256>>>(ppart, pc);

    // 5. h1 = relu(c @ Wd1 + bd1), split-K=2 (Kper=320) + reduce
    gemm_part<<<dim3(4, 32, 2), 256, GEMM_SMEM_1X>>>(
        pc, 640, Wd1, 256, ppd, 256, 320, 2048 * 256);
    red2<true><<<512, 256>>>(ppd, 2048 * 256, bd1, ph1, 256, 131072);

    // 6. out = h1 @ Wd2 + bd2, split-K=2 (Kper=128) + reduce
    gemm_part<<<dim3(2, 32, 2), 256, GEMM_SMEM_1X>>>(
        ph1, 256, Wd2, 128, ppd, 128, 128, 2048 * 128);
    red2<false><<<256, 256>>>(ppd, 2048 * 128, bd2, out, 128, 65536);
}

// round 13
// speedup vs baseline: 1.3018x; 1.1346x over previous
#include <cuda_runtime.h>
#include <stdint.h>

typedef unsigned long long ull;

// ---------------------------------------------------------------------------
// Scratch (device globals — no allocation allowed)
// ---------------------------------------------------------------------------
__device__ float g_Wall[128 * 384];    // [Uk | Uq | Wv] fp32
__device__ float g_ball[384];          // [ck+ba1 | cq | bv]
__device__ float g_hkq[2048 * 256];    // [hk | hq]
__device__ float g_w[8 * 1024 * 1024]; // attention weights, FRAGMENT layout:
                                       // per bh: block (g,ck) = 512 floats at
                                       // ((g*32+ck)*512); element = q*128+lane*4+kt
__device__ float g_c[2048 * 640];      // [v | o0..o3] fp32
__device__ float g_h1[2048 * 256];     // decoder hidden fp32
__device__ float g_part[4 * 8 * 1024 * 128];  // wv split-K partials
__device__ float g_pd[2 * 2048 * 256];        // dec split-K partials (reused)

// ---------------------------------------------------------------------------
// helpers
// ---------------------------------------------------------------------------
__device__ __forceinline__ ull pack2(float lo, float hi) {
    ull r; asm("mov.b64 %0, {%1, %2};" : "=l"(r) : "f"(lo), "f"(hi)); return r;
}
__device__ __forceinline__ void unpack2(ull v, float& lo, float& hi) {
    asm("mov.b64 {%0, %1}, %2;" : "=f"(lo), "=f"(hi) : "l"(v));
}
__device__ __forceinline__ ull fma2(ull a, ull b, ull c) {
    ull d; asm("fma.rn.f32x2 %0, %1, %2, %3;" : "=l"(d) : "l"(a), "l"(b), "l"(c)); return d;
}
__device__ __forceinline__ ull add2(ull a, ull b) {
    ull d; asm("add.rn.f32x2 %0, %1, %2;" : "=l"(d) : "l"(a), "l"(b)); return d;
}
__device__ __forceinline__ float rna_tf32(float x) {
    uint32_t r; asm("cvt.rna.tf32.f32 %0, %1;" : "=r"(r) : "f"(x));
    return __uint_as_float(r);
}
__device__ __forceinline__ void mma_tf32(float c[4],
    uint32_t a0, uint32_t a1, uint32_t a2, uint32_t a3,
    uint32_t b0, uint32_t b1)
{
    asm("mma.sync.aligned.m16n8k8.row.col.f32.tf32.tf32.f32 "
        "{%0,%1,%2,%3},{%4,%5,%6,%7},{%8,%9},{%0,%1,%2,%3};"
        : "+f"(c[0]), "+f"(c[1]), "+f"(c[2]), "+f"(c[3])
        : "r"(a0), "r"(a1), "r"(a2), "r"(a3), "r"(b0), "r"(b1));
}
__device__ __forceinline__ uint32_t fu(float x) { return __float_as_uint(x); }

// MUFU-free sigmoid (2 Newton iters on d in (1,2], rel err ~1e-5).
__device__ __forceinline__ float sigmoid_fma(float s) {
    float t = s * 1.4426950408889634f;
    float tn = -fabsf(t);
    tn = fmaxf(tn, -125.0f);
    float m = tn + 12582912.0f;
    int ib = __float_as_int(m);
    float n = m - 12582912.0f;
    float f = tn - n;
    float p = 1.33335581e-3f;
    p = fmaf(p, f, 9.61812910e-3f);
    p = fmaf(p, f, 5.55041087e-2f);
    p = fmaf(p, f, 2.40226507e-1f);
    p = fmaf(p, f, 6.93147181e-1f);
    p = fmaf(p, f, 1.0f);
    float scale = __int_as_float((ib - 0x4B400000 + 127) << 23);
    float e = p * scale;
    float d = 1.0f + e;
    float r = fmaf(d, -0.47058824f, 1.41176471f);
    r = r * fmaf(-d, r, 2.0f);
    r = r * fmaf(-d, r, 2.0f);
    float sn = e * r;
    return (s > 0.0f) ? (1.0f - sn) : sn;
}

// ---------------------------------------------------------------------------
// prep: fused [Uk|Uq|Wv] (fp32) + fused bias (ba1 folded into hk bias).
// ---------------------------------------------------------------------------
__global__ __launch_bounds__(256) void prep_kernel(
    const float* __restrict__ Wk, const float* __restrict__ bk,
    const float* __restrict__ Wq, const float* __restrict__ bq,
    const float* __restrict__ Wv, const float* __restrict__ bv,
    const float* __restrict__ Wa1, const float* __restrict__ ba1)
{
    __shared__ float wa[64 * 32];
    int tid = threadIdx.x;
    for (int i = tid; i < 64 * 32; i += 256) wa[i] = Wa1[i];
    __syncthreads();

    int stride = gridDim.x * 256;
    for (int idx = blockIdx.x * 256 + tid; idx < 128 * 128; idx += stride) {
        int d = idx >> 7, j = idx & 127;
        int hb = j & ~31, a = j & 31;
        float sk = 0.f, sq = 0.f;
        #pragma unroll
        for (int t = 0; t < 32; t++) {
            sk += Wk[d * 128 + hb + t] * wa[t * 32 + a];
            sq += Wq[d * 128 + hb + t] * wa[(32 + t) * 32 + a];
        }
        g_Wall[d * 384 + j]       = sk;
        g_Wall[d * 384 + 128 + j] = sq;
        g_Wall[d * 384 + 256 + j] = Wv[d * 128 + j];
    }
    if (blockIdx.x == 0 && tid < 128) {
        int hb = tid & ~31, a = tid & 31;
        float sk = 0.f, sq = 0.f;
        #pragma unroll
        for (int t = 0; t < 32; t++) {
            sk += bk[hb + t] * wa[t * 32 + a];
            sq += bq[hb + t] * wa[(32 + t) * 32 + a];
        }
        g_ball[tid]       = sk + ba1[a];
        g_ball[128 + tid] = sq;
        g_ball[256 + tid] = bv[tid];
    }
}

// ---------------------------------------------------------------------------
// score (dots fused): computes w and stores it in mma-FRAGMENT layout:
//   for element (i, j):  g = i>>4, rr = i&15, r = rr&7, hi8 = rr>>3
//                        ck = j>>5, kin = j&31, c4 = kin&3, hi4 = (kin>>2)&1,
//                        kt = kin>>3,  q = hi4*2 + hi8
//   addr = bh<<20 | (g*32+ck)*512 + q*128 + (r*4+c4)*4 + kt
// Block = 32 i x 256 j. grid (4 jt, 32 it, 8 bh) = 1024 blocks.
// ---------------------------------------------------------------------------
__global__ __launch_bounds__(256, 4) void score_kernel(
    const float* __restrict__ hkq,
    float* __restrict__ wbuf,
    const float* __restrict__ Wa2,
    const float* __restrict__ ba2)
{
    __shared__ float hk_s[32 * 36];
    __shared__ float kdot_s[32];
    __shared__ ull wa2s[16];

    int tid = threadIdx.x;
    int lane = tid & 31, w = tid >> 5;
    int jt = blockIdx.x, itile = blockIdx.y, bh = blockIdx.z;
    int b = bh >> 2, h = bh & 3;
    int ibase = itile * 32;
    int jloc = jt * 256 + w * 32 + lane;   // batch-local j, 0..1023
    size_t brow = (size_t)b * 1024;

    {   // hk tile: 32 rows x 32 a
        int row = tid >> 3, g = tid & 7;
        float4 f = *(const float4*)(hkq + (brow + ibase + row) * 256 + h * 32 + g * 4);
        *(float4*)&hk_s[row * 36 + g * 4] = f;
    }
    if (tid < 16) {
        float a0 = 0.5f * Wa2[2 * tid], a1 = 0.5f * Wa2[2 * tid + 1];
        wa2s[tid] = pack2(a0, a1);
    }

    ull qp[8][2];
    {
        const float* qr = hkq + (brow + jloc) * 256 + 128 + h * 32;
        #pragma unroll
        for (int a4 = 0; a4 < 8; a4++) {
            ulonglong2 u = *(const ulonglong2*)(qr + a4 * 4);
            qp[a4][0] = u.x; qp[a4][1] = u.y;
        }
    }
    float ba2v = ba2[0];
    __syncthreads();

    if (tid < 32) {
        float kd = ba2v;
        #pragma unroll
        for (int a4 = 0; a4 < 8; a4++) {
            ulonglong2 wp = *(const ulonglong2*)&wa2s[a4 * 2];
            float w0, w1, w2, w3;
            unpack2(wp.x, w0, w1);
            unpack2(wp.y, w2, w3);
            kd += hk_s[tid * 36 + a4 * 4 + 0] * w0;
            kd += hk_s[tid * 36 + a4 * 4 + 1] * w1;
            kd += hk_s[tid * 36 + a4 * 4 + 2] * w2;
            kd += hk_s[tid * 36 + a4 * 4 + 3] * w3;
        }
        kdot_s[tid] = kd;
    }
    float qd;
    {
        ull qacc = 0ULL;
        #pragma unroll
        for (int a4 = 0; a4 < 8; a4++) {
            ulonglong2 wp = *(const ulonglong2*)&wa2s[a4 * 2];
            qacc = fma2(qp[a4][0], wp.x, qacc);
            qacc = fma2(qp[a4][1], wp.y, qacc);
        }
        float q0, q1;
        unpack2(qacc, q0, q1);
        qd = q0 + q1;
    }
    __syncthreads();

    const ull ABSM = 0x7FFFFFFF7FFFFFFFULL;

    // fragment-layout store indices (j-dependent, loop-invariant)
    int ck  = jloc >> 5;
    int kin = jloc & 31;
    int c4j = kin & 3;
    int hi4 = (kin >> 2) & 1;
    int ktj = kin >> 3;
    float* wb = wbuf + ((size_t)bh << 20);
    int joff = hi4 * 256 + c4j * 4 + ktj;   // q-base (hi4*2)*128 + c4*4 + kt

    #pragma unroll 4
    for (int i = 0; i < 32; i++) {
        ull s0 = 0ULL, s1 = 0ULL;
        #pragma unroll
        for (int a4 = 0; a4 < 8; a4++) {
            ulonglong2 k = *(const ulonglong2*)&hk_s[i * 36 + a4 * 4];
            ulonglong2 wp = *(const ulonglong2*)&wa2s[a4 * 2];
            ull u0 = add2(k.x, qp[a4][0]);
            ull u1 = add2(k.y, qp[a4][1]);
            s0 = fma2(u0 & ABSM, wp.x, s0);
            s1 = fma2(u1 & ABSM, wp.y, s1);
        }
        float f0, f1, f2, f3;
        unpack2(s0, f0, f1);
        unpack2(s1, f2, f3);
        float s = kdot_s[i] + qd + ((f0 + f1) + (f2 + f3));
        int gi = ibase + i;
        if (gi == jloc) s -= 10000.f;
        int g = gi >> 4, rr = gi & 15;
        int rj = rr & 7, hi8 = rr >> 3;
        wb[(size_t)(g * 32 + ck) * 512 + hi8 * 128 + rj * 16 + joff] =
            rna_tf32(sigmoid_fma(s));
    }
}

// ---------------------------------------------------------------------------
// qkv GEMM (2-pass, exact A): 256 threads, 64x64 tile, double-buffered.
// ---------------------------------------------------------------------------
#define GEMM_SMEM_SPLIT 55296
#define GEMM_SMEM_1X    36864
#define GEMM_SMEM_WV    18432

__global__ __launch_bounds__(256, 2) void gemm_qkv(
    const float* __restrict__ A, int lda,
    const float* __restrict__ W, int ldw,
    const float* __restrict__ bias,
    float* __restrict__ C1, int ldc1,
    float* __restrict__ C2, int ldc2, int nsplit,
    int K)
{
    extern __shared__ float sm[];
    float* AsH = sm;
    float* AsL = sm + 4608;
    float* Bs  = sm + 9216;

    int tid = threadIdx.x;
    int lane = tid & 31, wq = tid >> 5;
    int wm = wq >> 2, wn = wq & 3;
    int r = lane >> 2, c4 = lane & 3;
    int m0 = blockIdx.y * 64, n0 = blockIdx.x * 64;

    float acc[2][2][4];
    #pragma unroll
    for (int i = 0; i < 2; i++)
        #pragma unroll
        for (int j = 0; j < 2; j++)
            #pragma unroll
            for (int e = 0; e < 4; e++) acc[i][j][e] = 0.f;

    int nch = K >> 5;

    int am[2], ak0[2], bn[2], bk0[2];
    #pragma unroll
    for (int s = 0; s < 2; s++) {
        int lin = tid + s * 256;
        am[s] = lin >> 3;  ak0[s] = lin & 7;
        bn[s] = lin & 63;  bk0[s] = lin >> 6;
    }

    float rA[2][4], rB[2][4];
    auto ldg_chunk = [&](int kc) {
        #pragma unroll
        for (int s = 0; s < 2; s++)
            #pragma unroll
            for (int u = 0; u < 4; u++) {
                rA[s][u] = A[(size_t)(m0 + am[s]) * lda + kc + ak0[s] + 8 * u];
                rB[s][u] = W[(size_t)(kc + bk0[s] + 8 * u) * ldw + n0 + bn[s]];
            }
    };
    auto store_chunk = [&](int buf) {
        float* aH = AsH + buf * 2304;
        float* aL = AsL + buf * 2304;
        float* bs = Bs  + buf * 2304;
        #pragma unroll
        for (int s = 0; s < 2; s++) {
            float4 h, l;
            h.x = rna_tf32(rA[s][0]); h.y = rna_tf32(rA[s][1]);
            h.z = rna_tf32(rA[s][2]); h.w = rna_tf32(rA[s][3]);
            l.x = rA[s][0] - h.x; l.y = rA[s][1] - h.y;
            l.z = rA[s][2] - h.z; l.w = rA[s][3] - h.w;
            *(float4*)&aH[am[s] * 36 + ak0[s] * 4] = h;
            *(float4*)&aL[am[s] * 36 + ak0[s] * 4] = l;
            float4 b;
            b.x = rna_tf32(rB[s][0]); b.y = rna_tf32(rB[s][1]);
            b.z = rna_tf32(rB[s][2]); b.w = rna_tf32(rB[s][3]);
            *(float4*)&bs[bn[s] * 36 + bk0[s] * 4] = b;
        }
    };

    ldg_chunk(0);
    store_chunk(0);
    __syncthreads();

    for (int ck = 0; ck < nch; ck++) {
        int p = ck & 1;
        if (ck + 1 < nch) ldg_chunk((ck + 1) << 5);

        const float* aHp = AsH + p * 2304;
        const float* aLp = AsL + p * 2304;
        const float* bsp = Bs  + p * 2304;

        float4 bH0[2], bH1[2];
        #pragma unroll
        for (int nt = 0; nt < 2; nt++) {
            int nb = wn * 16 + nt * 8 + r;
            bH0[nt] = *(const float4*)&bsp[nb * 36 + c4 * 4];
            bH1[nt] = *(const float4*)&bsp[nb * 36 + (c4 + 4) * 4];
        }
        #pragma unroll
        for (int mt = 0; mt < 2; mt++) {
            int rb = wm * 32 + mt * 16 + r;
            float4 aH[4], aL[4];
            aH[0] = *(const float4*)&aHp[rb * 36 + c4 * 4];
            aH[1] = *(const float4*)&aHp[(rb + 8) * 36 + c4 * 4];
            aH[2] = *(const float4*)&aHp[rb * 36 + (c4 + 4) * 4];
            aH[3] = *(const float4*)&aHp[(rb + 8) * 36 + (c4 + 4) * 4];
            aL[0] = *(const float4*)&aLp[rb * 36 + c4 * 4];
            aL[1] = *(const float4*)&aLp[(rb + 8) * 36 + c4 * 4];
            aL[2] = *(const float4*)&aLp[rb * 36 + (c4 + 4) * 4];
            aL[3] = *(const float4*)&aLp[(rb + 8) * 36 + (c4 + 4) * 4];
            #pragma unroll
            for (int kt = 0; kt < 4; kt++) {
                float ah0 = ((const float*)&aH[0])[kt], ah1 = ((const float*)&aH[1])[kt];
                float ah2 = ((const float*)&aH[2])[kt], ah3 = ((const float*)&aH[3])[kt];
                float al0 = ((const float*)&aL[0])[kt], al1 = ((const float*)&aL[1])[kt];
                float al2 = ((const float*)&aL[2])[kt], al3 = ((const float*)&aL[3])[kt];
                #pragma unroll
                for (int nt = 0; nt < 2; nt++) {
                    float bh0 = ((const float*)&bH0[nt])[kt], bh1 = ((const float*)&bH1[nt])[kt];
                    mma_tf32(acc[mt][nt], fu(ah0), fu(ah1), fu(ah2), fu(ah3), fu(bh0), fu(bh1));
                    mma_tf32(acc[mt][nt], fu(al0), fu(al1), fu(al2), fu(al3), fu(bh0), fu(bh1));
                }
            }
        }
        if (ck + 1 < nch) store_chunk(1 - p);
        __syncthreads();
    }

    bool left = (n0 < nsplit);
    float* Cb = left ? (C1 + n0) : (C2 + (n0 - nsplit));
    int ldc = left ? ldc1 : ldc2;

    #pragma unroll
    for (int mt = 0; mt < 2; mt++) {
        #pragma unroll
        for (int nt = 0; nt < 2; nt++) {
            int row = m0 + wm * 32 + mt * 16 + r;
            int col = wn * 16 + nt * 8 + 2 * c4;
            float2 bb = *(const float2*)(bias + n0 + col);
            float o0 = acc[mt][nt][0] + bb.x, o1 = acc[mt][nt][1] + bb.y;
            float o2 = acc[mt][nt][2] + bb.x, o3 = acc[mt][nt][3] + bb.y;
            *(float2*)(Cb + (size_t)row * ldc + col) = make_float2(o0, o1);
            *(float2*)(Cb + (size_t)(row + 8) * ldc + col) = make_float2(o2, o3);
        }
    }
}

// ---------------------------------------------------------------------------
// wv GEMM, split-K=4: A (w) fragments loaded DIRECTLY from gmem (fragment
// layout, coalesced LDG.128); only B (v) staged in smem.
// grid (2 n, 16 m, 32 z), z = bh*4 + sp.  smem = Bs[2][2304] = 18432 B.
// ---------------------------------------------------------------------------
__global__ __launch_bounds__(256, 3) void wv_gemm(
    const float* __restrict__ wbuf, const float* __restrict__ cbuf,
    float* __restrict__ part)
{
    extern __shared__ float sm[];
    float* Bs = sm;   // [2][2304]

    int tid = threadIdx.x;
    int lane = tid & 31, wq = tid >> 5;
    int wm = wq >> 2, wn = wq & 3;
    int r = lane >> 2, c4 = lane & 3;
    int m0 = blockIdx.y * 64, n0 = blockIdx.x * 64;
    int z = blockIdx.z;
    int bh = z >> 2, sp = z & 3;
    int b = bh >> 2;
    int kbase = sp << 8;
    int ckg0 = sp << 3;   // global chunk base

    const float* Wf = wbuf + ((size_t)bh << 20);
    const float* V = cbuf + (size_t)b * 1024 * 640;
    float* P = part + (size_t)z * 131072 + n0;

    float acc[2][2][4];
    #pragma unroll
    for (int i = 0; i < 2; i++)
        #pragma unroll
        for (int j = 0; j < 2; j++)
            #pragma unroll
            for (int e = 0; e < 4; e++) acc[i][j][e] = 0.f;

    int bn[2], bk0[2];
    #pragma unroll
    for (int s = 0; s < 2; s++) {
        int lin = tid + s * 256;
        bn[s] = lin & 63;  bk0[s] = lin >> 6;
    }

    // A fragment base addresses for the two mt groups (g = 16-row group)
    const float* afrag[2];
    #pragma unroll
    for (int mt = 0; mt < 2; mt++) {
        int g = (m0 + wm * 32 + mt * 16) >> 4;
        afrag[mt] = Wf + (size_t)g * 32 * 512 + lane * 4;
    }

    float rB[2][4];
    auto ldg_chunk = [&](int kc) {
        #pragma unroll
        for (int s = 0; s < 2; s++)
            #pragma unroll
            for (int u = 0; u < 4; u++)
                rB[s][u] = V[(size_t)(kc + bk0[s] + 8 * u) * 640 + n0 + bn[s]];
    };
    auto store_chunk = [&](int buf) {
        float* bs = Bs + buf * 2304;
        #pragma unroll
        for (int s = 0; s < 2; s++) {
            float4 bb;
            bb.x = rna_tf32(rB[s][0]); bb.y = rna_tf32(rB[s][1]);
            bb.z = rna_tf32(rB[s][2]); bb.w = rna_tf32(rB[s][3]);
            *(float4*)&bs[bn[s] * 36 + bk0[s] * 4] = bb;
        }
    };

    ldg_chunk(kbase);
    store_chunk(0);
    __syncthreads();

    for (int ck = 0; ck < 8; ck++) {
        int p = ck & 1;
        if (ck + 1 < 8) ldg_chunk(kbase + ((ck + 1) << 5));

        const float* bsp = Bs + p * 2304;

        float4 bH0[2], bH1[2];
        #pragma unroll
        for (int nt = 0; nt < 2; nt++) {
            int nb = wn * 16 + nt * 8 + r;
            bH0[nt] = *(const float4*)&bsp[nb * 36 + c4 * 4];
            bH1[nt] = *(const float4*)&bsp[nb * 36 + (c4 + 4) * 4];
        }
        #pragma unroll
        for (int mt = 0; mt < 2; mt++) {
            const float* ab = afrag[mt] + (size_t)(ckg0 + ck) * 512;
            float4 aH[4];
            aH[0] = *(const float4*)(ab);           // q=0: rows r,   k c4
            aH[1] = *(const float4*)(ab + 128);     // q=1: rows r+8, k c4
            aH[2] = *(const float4*)(ab + 256);     // q=2: rows r,   k c4+4
            aH[3] = *(const float4*)(ab + 384);     // q=3: rows r+8, k c4+4
            #pragma unroll
            for (int kt = 0; kt < 4; kt++) {
                float ah0 = ((const float*)&aH[0])[kt], ah1 = ((const float*)&aH[1])[kt];
                float ah2 = ((const float*)&aH[2])[kt], ah3 = ((const float*)&aH[3])[kt];
                #pragma unroll
                for (int nt = 0; nt < 2; nt++) {
                    float bh0 = ((const float*)&bH0[nt])[kt], bh1 = ((const float*)&bH1[nt])[kt];
                    mma_tf32(acc[mt][nt], fu(ah0), fu(ah1), fu(ah2), fu(ah3), fu(bh0), fu(bh1));
                }
            }
        }
        if (ck + 1 < 8) store_chunk(1 - p);
        __syncthreads();
    }

    #pragma unroll
    for (int mt = 0; mt < 2; mt++) {
        #pragma unroll
        for (int nt = 0; nt < 2; nt++) {
            int row = m0 + wm * 32 + mt * 16 + r;
            int col = wn * 16 + nt * 8 + 2 * c4;
            *(float2*)(P + (size_t)row * 128 + col) =
                make_float2(acc[mt][nt][0], acc[mt][nt][1]);
            *(float2*)(P + (size_t)(row + 8) * 128 + col) =
                make_float2(acc[mt][nt][2], acc[mt][nt][3]);
        }
    }
}

// wv reduce: sum 4 partials -> g_c cols [128,640).
__global__ __launch_bounds__(256) void wv_reduce(
    const float* __restrict__ part, float* __restrict__ cbuf)
{
    int i = blockIdx.x * 256 + threadIdx.x;   // f4 index
    if (i >= 8 * 1024 * 32) return;
    int bh = i >> 15;
    int rem = i & 32767;
    int row = rem >> 5, c4 = rem & 31;
    size_t base = ((size_t)bh * 4) * 131072 + row * 128 + c4 * 4;
    float4 s0 = *(const float4*)(part + base);
    float4 s1 = *(const float4*)(part + base + 131072);
    float4 s2 = *(const float4*)(part + base + 2 * 131072);
    float4 s3 = *(const float4*)(part + base + 3 * 131072);
    float4 o;
    o.x = (s0.x + s1.x) + (s2.x + s3.x);
    o.y = (s0.y + s1.y) + (s2.y + s3.y);
    o.z = (s0.z + s1.z) + (s2.z + s3.z);
    o.w = (s0.w + s1.w) + (s2.w + s3.w);
    int b = bh >> 2, h = bh & 3;
    *(float4*)(cbuf + (size_t)(b * 1024 + row) * 640 + 128 + h * 128 + c4 * 4) = o;
}

// ---------------------------------------------------------------------------
// gemm_part: split-K partial GEMM (single-pass tf32; A,B rounded at STS).
// ---------------------------------------------------------------------------
__global__ __launch_bounds__(256, 3) void gemm_part(
    const float* __restrict__ A, int lda,
    const float* __restrict__ W, int ldw,
    float* __restrict__ P, int N, int Kper, int partStride)
{
    extern __shared__ float sm[];
    float* As = sm;
    float* Bs = sm + 4608;

    int tid = threadIdx.x;
    int lane = tid & 31, wq = tid >> 5;
    int wm = wq >> 2, wn = wq & 3;
    int r = lane >> 2, c4 = lane & 3;
    int m0 = blockIdx.y * 64, n0 = blockIdx.x * 64;
    int kbase = blockIdx.z * Kper;
    float* Pz = P + (size_t)blockIdx.z * partStride + n0;

    float acc[2][2][4];
    #pragma unroll
    for (int i = 0; i < 2; i++)
        #pragma unroll
        for (int j = 0; j < 2; j++)
            #pragma unroll
            for (int e = 0; e < 4; e++) acc[i][j][e] = 0.f;

    int nch = Kper >> 5;

    int am[2], ak0[2], bn[2], bk0[2];
    #pragma unroll
    for (int s = 0; s < 2; s++) {
        int lin = tid + s * 256;
        am[s] = lin >> 3;  ak0[s] = lin & 7;
        bn[s] = lin & 63;  bk0[s] = lin >> 6;
    }

    float rA[2][4], rB[2][4];
    auto ldg_chunk = [&](int kc) {
        #pragma unroll
        for (int s = 0; s < 2; s++)
            #pragma unroll
            for (int u = 0; u < 4; u++) {
                rA[s][u] = A[(size_t)(m0 + am[s]) * lda + kc + ak0[s] + 8 * u];
                rB[s][u] = W[(size_t)(kc + bk0[s] + 8 * u) * ldw + n0 + bn[s]];
            }
    };
    auto store_chunk = [&](int buf) {
        float* as = As + buf * 2304;
        float* bs = Bs + buf * 2304;
        #pragma unroll
        for (int s = 0; s < 2; s++) {
            float4 a;
            a.x = rna_tf32(rA[s][0]); a.y = rna_tf32(rA[s][1]);
            a.z = rna_tf32(rA[s][2]); a.w = rna_tf32(rA[s][3]);
            *(float4*)&as[am[s] * 36 + ak0[s] * 4] = a;
            float4 bb;
            bb.x = rna_tf32(rB[s][0]); bb.y = rna_tf32(rB[s][1]);
            bb.z = rna_tf32(rB[s][2]); bb.w = rna_tf32(rB[s][3]);
            *(float4*)&bs[bn[s] * 36 + bk0[s] * 4] = bb;
        }
    };

    ldg_chunk(kbase);
    store_chunk(0);
    __syncthreads();

    for (int ck = 0; ck < nch; ck++) {
        int p = ck & 1;
        if (ck + 1 < nch) ldg_chunk(kbase + ((ck + 1) << 5));

        const float* asp = As + p * 2304;
        const float* bsp = Bs + p * 2304;

        float4 bH0[2], bH1[2];
        #pragma unroll
        for (int nt = 0; nt < 2; nt++) {
            int nb = wn * 16 + nt * 8 + r;
            bH0[nt] = *(const float4*)&bsp[nb * 36 + c4 * 4];
            bH1[nt] = *(const float4*)&bsp[nb * 36 + (c4 + 4) * 4];
        }
        #pragma unroll
        for (int mt = 0; mt < 2; mt++) {
            int rb = wm * 32 + mt * 16 + r;
            float4 aH[4];
            aH[0] = *(const float4*)&asp[rb * 36 + c4 * 4];
            aH[1] = *(const float4*)&asp[(rb + 8) * 36 + c4 * 4];
            aH[2] = *(const float4*)&asp[rb * 36 + (c4 + 4) * 4];
            aH[3] = *(const float4*)&asp[(rb + 8) * 36 + (c4 + 4) * 4];
            #pragma unroll
            for (int kt = 0; kt < 4; kt++) {
                float ah0 = ((const float*)&aH[0])[kt], ah1 = ((const float*)&aH[1])[kt];
                float ah2 = ((const float*)&aH[2])[kt], ah3 = ((const float*)&aH[3])[kt];
                #pragma unroll
                for (int nt = 0; nt < 2; nt++) {
                    float bh0 = ((const float*)&bH0[nt])[kt], bh1 = ((const float*)&bH1[nt])[kt];
                    mma_tf32(acc[mt][nt], fu(ah0), fu(ah1), fu(ah2), fu(ah3), fu(bh0), fu(bh1));
                }
            }
        }
        if (ck + 1 < nch) store_chunk(1 - p);
        __syncthreads();
    }

    #pragma unroll
    for (int mt = 0; mt < 2; mt++) {
        #pragma unroll
        for (int nt = 0; nt < 2; nt++) {
            int row = m0 + wm * 32 + mt * 16 + r;
            int col = wn * 16 + nt * 8 + 2 * c4;
            *(float2*)(Pz + (size_t)row * N + col) =
                make_float2(acc[mt][nt][0], acc[mt][nt][1]);
            *(float2*)(Pz + (size_t)(row + 8) * N + col) =
                make_float2(acc[mt][nt][2], acc[mt][nt][3]);
        }
    }
}

// red2: dst = act(p0 + p1 + bias), float4-vectorized.
template <bool RELU>
__global__ __launch_bounds__(256) void red2(
    const float* __restrict__ p, int partStride,
    const float* __restrict__ bias,
    float* __restrict__ dst, int ncols, int total4)
{
    int i = blockIdx.x * 256 + threadIdx.x;
    if (i >= total4) return;
    float4 a = *(const float4*)(p + (size_t)i * 4);
    float4 b = *(const float4*)(p + partStride + (size_t)i * 4);
    int col = (i * 4) & (ncols - 1);
    float4 bb = *(const float4*)(bias + col);
    float4 o;
    o.x = a.x + b.x + bb.x;
    o.y = a.y + b.y + bb.y;
    o.z = a.z + b.z + bb.z;
    o.w = a.w + b.w + bb.w;
    if (RELU) {
        o.x = fmaxf(o.x, 0.f); o.y = fmaxf(o.y, 0.f);
        o.z = fmaxf(o.z, 0.f); o.w = fmaxf(o.w, 0.f);
    }
    *(float4*)(dst + (size_t)i * 4) = o;
}

// ---------------------------------------------------------------------------
// launch
// ---------------------------------------------------------------------------
extern "C" void kernel_launch(void* const* d_in, const int* in_sizes, int n_in,
                              void* d_out, int out_size)
{
    const float* x   = (const float*)d_in[0];
    const float* Wk  = (const float*)d_in[1];
    const float* bk  = (const float*)d_in[2];
    const float* Wq  = (const float*)d_in[3];
    const float* bq  = (const float*)d_in[4];
    const float* Wv  = (const float*)d_in[5];
    const float* bv  = (const float*)d_in[6];
    const float* Wa1 = (const float*)d_in[7];
    const float* ba1 = (const float*)d_in[8];
    const float* Wa2 = (const float*)d_in[9];
    const float* ba2 = (const float*)d_in[10];
    const float* Wd1 = (const float*)d_in[11];
    const float* bd1 = (const float*)d_in[12];
    const float* Wd2 = (const float*)d_in[13];
    const float* bd2 = (const float*)d_in[14];
    float* out = (float*)d_out;

    float *pWall, *pball, *phkq, *pw, *pc, *ph1, *ppart, *ppd;
    cudaGetSymbolAddress((void**)&pWall, g_Wall);
    cudaGetSymbolAddress((void**)&pball, g_ball);
    cudaGetSymbolAddress((void**)&phkq, g_hkq);
    cudaGetSymbolAddress((void**)&pw,   g_w);
    cudaGetSymbolAddress((void**)&pc,   g_c);
    cudaGetSymbolAddress((void**)&ph1,  g_h1);
    cudaGetSymbolAddress((void**)&ppart, g_part);
    cudaGetSymbolAddress((void**)&ppd,  g_pd);

    cudaFuncSetAttribute((const void*)gemm_qkv,
                         cudaFuncAttributeMaxDynamicSharedMemorySize, GEMM_SMEM_SPLIT);
    cudaFuncSetAttribute((const void*)wv_gemm,
                         cudaFuncAttributeMaxDynamicSharedMemorySize, GEMM_SMEM_WV);
    cudaFuncSetAttribute((const void*)gemm_part,
                         cudaFuncAttributeMaxDynamicSharedMemorySize, GEMM_SMEM_1X);

    // 1. fused effective weights + biases
    prep_kernel<<<32, 256>>>(Wk, bk, Wq, bq, Wv, bv, Wa1, ba1);

    // 2. [hk|hq|v] = x @ Wall + ball   (2-pass: exact A)
    gemm_qkv<<<dim3(6, 32), 256, GEMM_SMEM_SPLIT>>>(
        x, 128, pWall, 384, pball, phkq, 256, pc, 640, 256, 128);

    // 3. attention scores (dots fused) -> g_w in mma-fragment layout
    score_kernel<<<dim3(4, 32, 8), 256>>>(phkq, pw, Wa2, ba2);

    // 4. o = w @ v, split-K=4 (A direct from gmem) -> partials, then reduce
    wv_gemm<<<dim3(2, 16, 32), 256, GEMM_SMEM_WV>>>(pw, pc, ppart);
    wv_reduce<<<1024, 256>>>(ppart, pc);

    // 5. h1 = relu(c @ Wd1 + bd1), split-K=2 (Kper=320) + reduce
    gemm_part<<<dim3(4, 32, 2), 256, GEMM_SMEM_1X>>>(
        pc, 640, Wd1, 256, ppd, 256, 320, 2048 * 256);
    red2<true><<<512, 256>>>(ppd, 2048 * 256, bd1, ph1, 256, 131072);

    // 6. out = h1 @ Wd2 + bd2, split-K=2 (Kper=128) + reduce
    gemm_part<<<dim3(2, 32, 2), 256, GEMM_SMEM_1X>>>(
        ph1, 256, Wd2, 128, ppd, 128, 128, 2048 * 128);
    red2<false><<<256, 256>>>(ppd, 2048 * 128, bd2, out, 128, 65536);
}

// round 14
// speedup vs baseline: 1.3481x; 1.0356x over previous
#include <cuda_runtime.h>
#include <stdint.h>

typedef unsigned long long ull;

// ---------------------------------------------------------------------------
// Scratch (device globals — no allocation allowed)
// ---------------------------------------------------------------------------
__device__ float g_Wall[128 * 384];    // [Uk | Uq | Wv] fp32
__device__ float g_ball[384];          // [ck+ba1 | cq | bv]
__device__ float g_hkq[2048 * 256];    // [hk | hq]
__device__ float g_w[8 * 1024 * 1024]; // attention weights, FRAGMENT layout:
                                       // per bh: block (g,ck) = 512 floats at
                                       // ((g*32+ck)*512); element = q*128+lane*4+kt
__device__ float g_c[2048 * 640];      // [v | o0..o3] fp32
__device__ float g_h1[2048 * 256];     // decoder hidden fp32
__device__ float g_part[4 * 8 * 1024 * 128];  // wv split-K partials
__device__ float g_pd[2 * 2048 * 256];        // dec split-K partials (reused)

// ---------------------------------------------------------------------------
// helpers
// ---------------------------------------------------------------------------
__device__ __forceinline__ ull pack2(float lo, float hi) {
    ull r; asm("mov.b64 %0, {%1, %2};" : "=l"(r) : "f"(lo), "f"(hi)); return r;
}
__device__ __forceinline__ void unpack2(ull v, float& lo, float& hi) {
    asm("mov.b64 {%0, %1}, %2;" : "=f"(lo), "=f"(hi) : "l"(v));
}
__device__ __forceinline__ ull fma2(ull a, ull b, ull c) {
    ull d; asm("fma.rn.f32x2 %0, %1, %2, %3;" : "=l"(d) : "l"(a), "l"(b), "l"(c)); return d;
}
__device__ __forceinline__ ull add2(ull a, ull b) {
    ull d; asm("add.rn.f32x2 %0, %1, %2;" : "=l"(d) : "l"(a), "l"(b)); return d;
}
__device__ __forceinline__ float rna_tf32(float x) {
    uint32_t r; asm("cvt.rna.tf32.f32 %0, %1;" : "=r"(r) : "f"(x));
    return __uint_as_float(r);
}
__device__ __forceinline__ void mma_tf32(float c[4],
    uint32_t a0, uint32_t a1, uint32_t a2, uint32_t a3,
    uint32_t b0, uint32_t b1)
{
    asm("mma.sync.aligned.m16n8k8.row.col.f32.tf32.tf32.f32 "
        "{%0,%1,%2,%3},{%4,%5,%6,%7},{%8,%9},{%0,%1,%2,%3};"
        : "+f"(c[0]), "+f"(c[1]), "+f"(c[2]), "+f"(c[3])
        : "r"(a0), "r"(a1), "r"(a2), "r"(a3), "r"(b0), "r"(b1));
}
__device__ __forceinline__ uint32_t fu(float x) { return __float_as_uint(x); }

// MUFU-free sigmoid (2 Newton iters on d in (1,2], rel err ~1e-5).
__device__ __forceinline__ float sigmoid_fma(float s) {
    float t = s * 1.4426950408889634f;
    float tn = -fabsf(t);
    tn = fmaxf(tn, -125.0f);
    float m = tn + 12582912.0f;
    int ib = __float_as_int(m);
    float n = m - 12582912.0f;
    float f = tn - n;
    float p = 1.33335581e-3f;
    p = fmaf(p, f, 9.61812910e-3f);
    p = fmaf(p, f, 5.55041087e-2f);
    p = fmaf(p, f, 2.40226507e-1f);
    p = fmaf(p, f, 6.93147181e-1f);
    p = fmaf(p, f, 1.0f);
    float scale = __int_as_float((ib - 0x4B400000 + 127) << 23);
    float e = p * scale;
    float d = 1.0f + e;
    float r = fmaf(d, -0.47058824f, 1.41176471f);
    r = r * fmaf(-d, r, 2.0f);
    r = r * fmaf(-d, r, 2.0f);
    float sn = e * r;
    return (s > 0.0f) ? (1.0f - sn) : sn;
}

// ---------------------------------------------------------------------------
// prep: fused [Uk|Uq|Wv] (fp32) + fused bias (ba1 folded into hk bias).
// ---------------------------------------------------------------------------
__global__ __launch_bounds__(256) void prep_kernel(
    const float* __restrict__ Wk, const float* __restrict__ bk,
    const float* __restrict__ Wq, const float* __restrict__ bq,
    const float* __restrict__ Wv, const float* __restrict__ bv,
    const float* __restrict__ Wa1, const float* __restrict__ ba1)
{
    __shared__ float wa[64 * 32];
    int tid = threadIdx.x;
    for (int i = tid; i < 64 * 32; i += 256) wa[i] = Wa1[i];
    __syncthreads();

    int stride = gridDim.x * 256;
    for (int idx = blockIdx.x * 256 + tid; idx < 128 * 128; idx += stride) {
        int d = idx >> 7, j = idx & 127;
        int hb = j & ~31, a = j & 31;
        float sk = 0.f, sq = 0.f;
        #pragma unroll
        for (int t = 0; t < 32; t++) {
            sk += Wk[d * 128 + hb + t] * wa[t * 32 + a];
            sq += Wq[d * 128 + hb + t] * wa[(32 + t) * 32 + a];
        }
        g_Wall[d * 384 + j]       = sk;
        g_Wall[d * 384 + 128 + j] = sq;
        g_Wall[d * 384 + 256 + j] = Wv[d * 128 + j];
    }
    if (blockIdx.x == 0 && tid < 128) {
        int hb = tid & ~31, a = tid & 31;
        float sk = 0.f, sq = 0.f;
        #pragma unroll
        for (int t = 0; t < 32; t++) {
            sk += bk[hb + t] * wa[t * 32 + a];
            sq += bq[hb + t] * wa[(32 + t) * 32 + a];
        }
        g_ball[tid]       = sk + ba1[a];
        g_ball[128 + tid] = sq;
        g_ball[256 + tid] = bv[tid];
    }
}

// ---------------------------------------------------------------------------
// score (dots fused): computes w, stores in mma-FRAGMENT layout.
// Block = 32 i x 256 j. grid (4 jt, 32 it, 8 bh) = 1024 blocks.
// ---------------------------------------------------------------------------
__global__ __launch_bounds__(256, 4) void score_kernel(
    const float* __restrict__ hkq,
    float* __restrict__ wbuf,
    const float* __restrict__ Wa2,
    const float* __restrict__ ba2)
{
    __shared__ float hk_s[32 * 36];
    __shared__ float kdot_s[32];
    __shared__ ull wa2s[16];

    int tid = threadIdx.x;
    int lane = tid & 31, w = tid >> 5;
    int jt = blockIdx.x, itile = blockIdx.y, bh = blockIdx.z;
    int b = bh >> 2, h = bh & 3;
    int ibase = itile * 32;
    int jloc = jt * 256 + w * 32 + lane;
    size_t brow = (size_t)b * 1024;

    {   // hk tile: 32 rows x 32 a
        int row = tid >> 3, g = tid & 7;
        float4 f = *(const float4*)(hkq + (brow + ibase + row) * 256 + h * 32 + g * 4);
        *(float4*)&hk_s[row * 36 + g * 4] = f;
    }
    if (tid < 16) {
        float a0 = 0.5f * Wa2[2 * tid], a1 = 0.5f * Wa2[2 * tid + 1];
        wa2s[tid] = pack2(a0, a1);
    }

    ull qp[8][2];
    {
        const float* qr = hkq + (brow + jloc) * 256 + 128 + h * 32;
        #pragma unroll
        for (int a4 = 0; a4 < 8; a4++) {
            ulonglong2 u = *(const ulonglong2*)(qr + a4 * 4);
            qp[a4][0] = u.x; qp[a4][1] = u.y;
        }
    }
    float ba2v = ba2[0];
    __syncthreads();

    if (tid < 32) {
        float kd = ba2v;
        #pragma unroll
        for (int a4 = 0; a4 < 8; a4++) {
            ulonglong2 wp = *(const ulonglong2*)&wa2s[a4 * 2];
            float w0, w1, w2, w3;
            unpack2(wp.x, w0, w1);
            unpack2(wp.y, w2, w3);
            kd += hk_s[tid * 36 + a4 * 4 + 0] * w0;
            kd += hk_s[tid * 36 + a4 * 4 + 1] * w1;
            kd += hk_s[tid * 36 + a4 * 4 + 2] * w2;
            kd += hk_s[tid * 36 + a4 * 4 + 3] * w3;
        }
        kdot_s[tid] = kd;
    }
    float qd;
    {
        ull qacc = 0ULL;
        #pragma unroll
        for (int a4 = 0; a4 < 8; a4++) {
            ulonglong2 wp = *(const ulonglong2*)&wa2s[a4 * 2];
            qacc = fma2(qp[a4][0], wp.x, qacc);
            qacc = fma2(qp[a4][1], wp.y, qacc);
        }
        float q0, q1;
        unpack2(qacc, q0, q1);
        qd = q0 + q1;
    }
    __syncthreads();

    const ull ABSM = 0x7FFFFFFF7FFFFFFFULL;

    int ck  = jloc >> 5;
    int kin = jloc & 31;
    int c4j = kin & 3;
    int hi4 = (kin >> 2) & 1;
    int ktj = kin >> 3;
    float* wb = wbuf + ((size_t)bh << 20);
    int joff = hi4 * 256 + c4j * 4 + ktj;

    #pragma unroll 4
    for (int i = 0; i < 32; i++) {
        ull s0 = 0ULL, s1 = 0ULL;
        #pragma unroll
        for (int a4 = 0; a4 < 8; a4++) {
            ulonglong2 k = *(const ulonglong2*)&hk_s[i * 36 + a4 * 4];
            ulonglong2 wp = *(const ulonglong2*)&wa2s[a4 * 2];
            ull u0 = add2(k.x, qp[a4][0]);
            ull u1 = add2(k.y, qp[a4][1]);
            s0 = fma2(u0 & ABSM, wp.x, s0);
            s1 = fma2(u1 & ABSM, wp.y, s1);
        }
        float f0, f1, f2, f3;
        unpack2(s0, f0, f1);
        unpack2(s1, f2, f3);
        float s = kdot_s[i] + qd + ((f0 + f1) + (f2 + f3));
        int gi = ibase + i;
        if (gi == jloc) s -= 10000.f;
        int g = gi >> 4, rr = gi & 15;
        int rj = rr & 7, hi8 = rr >> 3;
        wb[(size_t)(g * 32 + ck) * 512 + hi8 * 128 + rj * 16 + joff] =
            rna_tf32(sigmoid_fma(s));
    }
}

// ---------------------------------------------------------------------------
// qkv GEMM (2-pass, exact A): 256 threads, 64x64 tile, double-buffered.
// ---------------------------------------------------------------------------
#define GEMM_SMEM_SPLIT 55296
#define GEMM_SMEM_1X    36864
#define GEMM_SMEM_WV    36864

__global__ __launch_bounds__(256, 2) void gemm_qkv(
    const float* __restrict__ A, int lda,
    const float* __restrict__ W, int ldw,
    const float* __restrict__ bias,
    float* __restrict__ C1, int ldc1,
    float* __restrict__ C2, int ldc2, int nsplit,
    int K)
{
    extern __shared__ float sm[];
    float* AsH = sm;
    float* AsL = sm + 4608;
    float* Bs  = sm + 9216;

    int tid = threadIdx.x;
    int lane = tid & 31, wq = tid >> 5;
    int wm = wq >> 2, wn = wq & 3;
    int r = lane >> 2, c4 = lane & 3;
    int m0 = blockIdx.y * 64, n0 = blockIdx.x * 64;

    float acc[2][2][4];
    #pragma unroll
    for (int i = 0; i < 2; i++)
        #pragma unroll
        for (int j = 0; j < 2; j++)
            #pragma unroll
            for (int e = 0; e < 4; e++) acc[i][j][e] = 0.f;

    int nch = K >> 5;

    int am[2], ak0[2], bn[2], bk0[2];
    #pragma unroll
    for (int s = 0; s < 2; s++) {
        int lin = tid + s * 256;
        am[s] = lin >> 3;  ak0[s] = lin & 7;
        bn[s] = lin & 63;  bk0[s] = lin >> 6;
    }

    float rA[2][4], rB[2][4];
    auto ldg_chunk = [&](int kc) {
        #pragma unroll
        for (int s = 0; s < 2; s++)
            #pragma unroll
            for (int u = 0; u < 4; u++) {
                rA[s][u] = A[(size_t)(m0 + am[s]) * lda + kc + ak0[s] + 8 * u];
                rB[s][u] = W[(size_t)(kc + bk0[s] + 8 * u) * ldw + n0 + bn[s]];
            }
    };
    auto store_chunk = [&](int buf) {
        float* aH = AsH + buf * 2304;
        float* aL = AsL + buf * 2304;
        float* bs = Bs  + buf * 2304;
        #pragma unroll
        for (int s = 0; s < 2; s++) {
            float4 h, l;
            h.x = rna_tf32(rA[s][0]); h.y = rna_tf32(rA[s][1]);
            h.z = rna_tf32(rA[s][2]); h.w = rna_tf32(rA[s][3]);
            l.x = rA[s][0] - h.x; l.y = rA[s][1] - h.y;
            l.z = rA[s][2] - h.z; l.w = rA[s][3] - h.w;
            *(float4*)&aH[am[s] * 36 + ak0[s] * 4] = h;
            *(float4*)&aL[am[s] * 36 + ak0[s] * 4] = l;
            float4 b;
            b.x = rna_tf32(rB[s][0]); b.y = rna_tf32(rB[s][1]);
            b.z = rna_tf32(rB[s][2]); b.w = rna_tf32(rB[s][3]);
            *(float4*)&bs[bn[s] * 36 + bk0[s] * 4] = b;
        }
    };

    ldg_chunk(0);
    store_chunk(0);
    __syncthreads();

    for (int ck = 0; ck < nch; ck++) {
        int p = ck & 1;
        if (ck + 1 < nch) ldg_chunk((ck + 1) << 5);

        const float* aHp = AsH + p * 2304;
        const float* aLp = AsL + p * 2304;
        const float* bsp = Bs  + p * 2304;

        float4 bH0[2], bH1[2];
        #pragma unroll
        for (int nt = 0; nt < 2; nt++) {
            int nb = wn * 16 + nt * 8 + r;
            bH0[nt] = *(const float4*)&bsp[nb * 36 + c4 * 4];
            bH1[nt] = *(const float4*)&bsp[nb * 36 + (c4 + 4) * 4];
        }
        #pragma unroll
        for (int mt = 0; mt < 2; mt++) {
            int rb = wm * 32 + mt * 16 + r;
            float4 aH[4], aL[4];
            aH[0] = *(const float4*)&aHp[rb * 36 + c4 * 4];
            aH[1] = *(const float4*)&aHp[(rb + 8) * 36 + c4 * 4];
            aH[2] = *(const float4*)&aHp[rb * 36 + (c4 + 4) * 4];
            aH[3] = *(const float4*)&aHp[(rb + 8) * 36 + (c4 + 4) * 4];
            aL[0] = *(const float4*)&aLp[rb * 36 + c4 * 4];
            aL[1] = *(const float4*)&aLp[(rb + 8) * 36 + c4 * 4];
            aL[2] = *(const float4*)&aLp[rb * 36 + (c4 + 4) * 4];
            aL[3] = *(const float4*)&aLp[(rb + 8) * 36 + (c4 + 4) * 4];
            #pragma unroll
            for (int kt = 0; kt < 4; kt++) {
                float ah0 = ((const float*)&aH[0])[kt], ah1 = ((const float*)&aH[1])[kt];
                float ah2 = ((const float*)&aH[2])[kt], ah3 = ((const float*)&aH[3])[kt];
                float al0 = ((const float*)&aL[0])[kt], al1 = ((const float*)&aL[1])[kt];
                float al2 = ((const float*)&aL[2])[kt], al3 = ((const float*)&aL[3])[kt];
                #pragma unroll
                for (int nt = 0; nt < 2; nt++) {
                    float bh0 = ((const float*)&bH0[nt])[kt], bh1 = ((const float*)&bH1[nt])[kt];
                    mma_tf32(acc[mt][nt], fu(ah0), fu(ah1), fu(ah2), fu(ah3), fu(bh0), fu(bh1));
                    mma_tf32(acc[mt][nt], fu(al0), fu(al1), fu(al2), fu(al3), fu(bh0), fu(bh1));
                }
            }
        }
        if (ck + 1 < nch) store_chunk(1 - p);
        __syncthreads();
    }

    bool left = (n0 < nsplit);
    float* Cb = left ? (C1 + n0) : (C2 + (n0 - nsplit));
    int ldc = left ? ldc1 : ldc2;

    #pragma unroll
    for (int mt = 0; mt < 2; mt++) {
        #pragma unroll
        for (int nt = 0; nt < 2; nt++) {
            int row = m0 + wm * 32 + mt * 16 + r;
            int col = wn * 16 + nt * 8 + 2 * c4;
            float2 bb = *(const float2*)(bias + n0 + col);
            float o0 = acc[mt][nt][0] + bb.x, o1 = acc[mt][nt][1] + bb.y;
            float o2 = acc[mt][nt][2] + bb.x, o3 = acc[mt][nt][3] + bb.y;
            *(float2*)(Cb + (size_t)row * ldc + col) = make_float2(o0, o1);
            *(float2*)(Cb + (size_t)(row + 8) * ldc + col) = make_float2(o2, o3);
        }
    }
}

// ---------------------------------------------------------------------------
// wv GEMM, split-K=4, FULL-N tile (64m x 128n): A (w) fragments from gmem
// (fragment layout, loaded ONCE per chunk, reused across 4 nt groups);
// only B (v) staged in smem.  grid (16 m, 32 z), z = bh*4 + sp.
// Warps: 2m x 4n, each warp n=32 (4 nt of 8).  smem Bs[2][128*36] = 36864 B.
// ---------------------------------------------------------------------------
__global__ __launch_bounds__(256, 2) void wv_gemm(
    const float* __restrict__ wbuf, const float* __restrict__ cbuf,
    float* __restrict__ part)
{
    extern __shared__ float sm[];
    float* Bs = sm;   // [2][4608]

    int tid = threadIdx.x;
    int lane = tid & 31, wq = tid >> 5;
    int wm = wq >> 2, wn = wq & 3;
    int r = lane >> 2, c4 = lane & 3;
    int m0 = blockIdx.x * 64;
    int z = blockIdx.y;
    int bh = z >> 2, sp = z & 3;
    int b = bh >> 2;
    int kbase = sp << 8;
    int ckg0 = sp << 3;

    const float* Wf = wbuf + ((size_t)bh << 20);
    const float* V = cbuf + (size_t)b * 1024 * 640;
    float* P = part + (size_t)z * 131072;

    float acc[2][4][4];
    #pragma unroll
    for (int i = 0; i < 2; i++)
        #pragma unroll
        for (int j = 0; j < 4; j++)
            #pragma unroll
            for (int e = 0; e < 4; e++) acc[i][j][e] = 0.f;

    int bn[4], bk0[4];
    #pragma unroll
    for (int s = 0; s < 4; s++) {
        int lin = tid + s * 256;      // 1024 slots: 128 n x 8 k-groups
        bn[s] = lin & 127;  bk0[s] = lin >> 7;
    }

    const float* afrag[2];
    #pragma unroll
    for (int mt = 0; mt < 2; mt++) {
        int g = (m0 + wm * 32 + mt * 16) >> 4;
        afrag[mt] = Wf + (size_t)g * 32 * 512 + lane * 4;
    }

    float rB[4][4];
    auto ldg_chunk = [&](int kc) {
        #pragma unroll
        for (int s = 0; s < 4; s++)
            #pragma unroll
            for (int u = 0; u < 4; u++)
                rB[s][u] = V[(size_t)(kc + bk0[s] + 8 * u) * 640 + bn[s]];
    };
    auto store_chunk = [&](int buf) {
        float* bs = Bs + buf * 4608;
        #pragma unroll
        for (int s = 0; s < 4; s++) {
            float4 bb;
            bb.x = rna_tf32(rB[s][0]); bb.y = rna_tf32(rB[s][1]);
            bb.z = rna_tf32(rB[s][2]); bb.w = rna_tf32(rB[s][3]);
            *(float4*)&bs[bn[s] * 36 + bk0[s] * 4] = bb;
        }
    };

    ldg_chunk(kbase);
    store_chunk(0);
    __syncthreads();

    for (int ck = 0; ck < 8; ck++) {
        int p = ck & 1;
        if (ck + 1 < 8) ldg_chunk(kbase + ((ck + 1) << 5));

        const float* bsp = Bs + p * 4608;

        float4 bH0[4], bH1[4];
        #pragma unroll
        for (int nt = 0; nt < 4; nt++) {
            int nb = wn * 32 + nt * 8 + r;
            bH0[nt] = *(const float4*)&bsp[nb * 36 + c4 * 4];
            bH1[nt] = *(const float4*)&bsp[nb * 36 + (c4 + 4) * 4];
        }
        #pragma unroll
        for (int mt = 0; mt < 2; mt++) {
            const float* ab = afrag[mt] + (size_t)(ckg0 + ck) * 512;
            float4 aH[4];
            aH[0] = *(const float4*)(ab);
            aH[1] = *(const float4*)(ab + 128);
            aH[2] = *(const float4*)(ab + 256);
            aH[3] = *(const float4*)(ab + 384);
            #pragma unroll
            for (int kt = 0; kt < 4; kt++) {
                float ah0 = ((const float*)&aH[0])[kt], ah1 = ((const float*)&aH[1])[kt];
                float ah2 = ((const float*)&aH[2])[kt], ah3 = ((const float*)&aH[3])[kt];
                #pragma unroll
                for (int nt = 0; nt < 4; nt++) {
                    float bh0 = ((const float*)&bH0[nt])[kt], bh1 = ((const float*)&bH1[nt])[kt];
                    mma_tf32(acc[mt][nt], fu(ah0), fu(ah1), fu(ah2), fu(ah3), fu(bh0), fu(bh1));
                }
            }
        }
        if (ck + 1 < 8) store_chunk(1 - p);
        __syncthreads();
    }

    #pragma unroll
    for (int mt = 0; mt < 2; mt++) {
        #pragma unroll
        for (int nt = 0; nt < 4; nt++) {
            int row = m0 + wm * 32 + mt * 16 + r;
            int col = wn * 32 + nt * 8 + 2 * c4;
            *(float2*)(P + (size_t)row * 128 + col) =
                make_float2(acc[mt][nt][0], acc[mt][nt][1]);
            *(float2*)(P + (size_t)(row + 8) * 128 + col) =
                make_float2(acc[mt][nt][2], acc[mt][nt][3]);
        }
    }
}

// wv reduce: sum 4 partials -> g_c cols [128,640).
__global__ __launch_bounds__(256) void wv_reduce(
    const float* __restrict__ part, float* __restrict__ cbuf)
{
    int i = blockIdx.x * 256 + threadIdx.x;   // f4 index
    if (i >= 8 * 1024 * 32) return;
    int bh = i >> 15;
    int rem = i & 32767;
    int row = rem >> 5, c4 = rem & 31;
    size_t base = ((size_t)bh * 4) * 131072 + row * 128 + c4 * 4;
    float4 s0 = *(const float4*)(part + base);
    float4 s1 = *(const float4*)(part + base + 131072);
    float4 s2 = *(const float4*)(part + base + 2 * 131072);
    float4 s3 = *(const float4*)(part + base + 3 * 131072);
    float4 o;
    o.x = (s0.x + s1.x) + (s2.x + s3.x);
    o.y = (s0.y + s1.y) + (s2.y + s3.y);
    o.z = (s0.z + s1.z) + (s2.z + s3.z);
    o.w = (s0.w + s1.w) + (s2.w + s3.w);
    int b = bh >> 2, h = bh & 3;
    *(float4*)(cbuf + (size_t)(b * 1024 + row) * 640 + 128 + h * 128 + c4 * 4) = o;
}

// ---------------------------------------------------------------------------
// gemm_part: split-K partial GEMM (single-pass tf32; A,B rounded at STS).
// ---------------------------------------------------------------------------
__global__ __launch_bounds__(256, 3) void gemm_part(
    const float* __restrict__ A, int lda,
    const float* __restrict__ W, int ldw,
    float* __restrict__ P, int N, int Kper, int partStride)
{
    extern __shared__ float sm[];
    float* As = sm;
    float* Bs = sm + 4608;

    int tid = threadIdx.x;
    int lane = tid & 31, wq = tid >> 5;
    int wm = wq >> 2, wn = wq & 3;
    int r = lane >> 2, c4 = lane & 3;
    int m0 = blockIdx.y * 64, n0 = blockIdx.x * 64;
    int kbase = blockIdx.z * Kper;
    float* Pz = P + (size_t)blockIdx.z * partStride + n0;

    float acc[2][2][4];
    #pragma unroll
    for (int i = 0; i < 2; i++)
        #pragma unroll
        for (int j = 0; j < 2; j++)
            #pragma unroll
            for (int e = 0; e < 4; e++) acc[i][j][e] = 0.f;

    int nch = Kper >> 5;

    int am[2], ak0[2], bn[2], bk0[2];
    #pragma unroll
    for (int s = 0; s < 2; s++) {
        int lin = tid + s * 256;
        am[s] = lin >> 3;  ak0[s] = lin & 7;
        bn[s] = lin & 63;  bk0[s] = lin >> 6;
    }

    float rA[2][4], rB[2][4];
    auto ldg_chunk = [&](int kc) {
        #pragma unroll
        for (int s = 0; s < 2; s++)
            #pragma unroll
            for (int u = 0; u < 4; u++) {
                rA[s][u] = A[(size_t)(m0 + am[s]) * lda + kc + ak0[s] + 8 * u];
                rB[s][u] = W[(size_t)(kc + bk0[s] + 8 * u) * ldw + n0 + bn[s]];
            }
    };
    auto store_chunk = [&](int buf) {
        float* as = As + buf * 2304;
        float* bs = Bs + buf * 2304;
        #pragma unroll
        for (int s = 0; s < 2; s++) {
            float4 a;
            a.x = rna_tf32(rA[s][0]); a.y = rna_tf32(rA[s][1]);
            a.z = rna_tf32(rA[s][2]); a.w = rna_tf32(rA[s][3]);
            *(float4*)&as[am[s] * 36 + ak0[s] * 4] = a;
            float4 bb;
            bb.x = rna_tf32(rB[s][0]); bb.y = rna_tf32(rB[s][1]);
            bb.z = rna_tf32(rB[s][2]); bb.w = rna_tf32(rB[s][3]);
            *(float4*)&bs[bn[s] * 36 + bk0[s] * 4] = bb;
        }
    };

    ldg_chunk(kbase);
    store_chunk(0);
    __syncthreads();

    for (int ck = 0; ck < nch; ck++) {
        int p = ck & 1;
        if (ck + 1 < nch) ldg_chunk(kbase + ((ck + 1) << 5));

        const float* asp = As + p * 2304;
        const float* bsp = Bs + p * 2304;

        float4 bH0[2], bH1[2];
        #pragma unroll
        for (int nt = 0; nt < 2; nt++) {
            int nb = wn * 16 + nt * 8 + r;
            bH0[nt] = *(const float4*)&bsp[nb * 36 + c4 * 4];
            bH1[nt] = *(const float4*)&bsp[nb * 36 + (c4 + 4) * 4];
        }
        #pragma unroll
        for (int mt = 0; mt < 2; mt++) {
            int rb = wm * 32 + mt * 16 + r;
            float4 aH[4];
            aH[0] = *(const float4*)&asp[rb * 36 + c4 * 4];
            aH[1] = *(const float4*)&asp[(rb + 8) * 36 + c4 * 4];
            aH[2] = *(const float4*)&asp[rb * 36 + (c4 + 4) * 4];
            aH[3] = *(const float4*)&asp[(rb + 8) * 36 + (c4 + 4) * 4];
            #pragma unroll
            for (int kt = 0; kt < 4; kt++) {
                float ah0 = ((const float*)&aH[0])[kt], ah1 = ((const float*)&aH[1])[kt];
                float ah2 = ((const float*)&aH[2])[kt], ah3 = ((const float*)&aH[3])[kt];
                #pragma unroll
                for (int nt = 0; nt < 2; nt++) {
                    float bh0 = ((const float*)&bH0[nt])[kt], bh1 = ((const float*)&bH1[nt])[kt];
                    mma_tf32(acc[mt][nt], fu(ah0), fu(ah1), fu(ah2), fu(ah3), fu(bh0), fu(bh1));
                }
            }
        }
        if (ck + 1 < nch) store_chunk(1 - p);
        __syncthreads();
    }

    #pragma unroll
    for (int mt = 0; mt < 2; mt++) {
        #pragma unroll
        for (int nt = 0; nt < 2; nt++) {
            int row = m0 + wm * 32 + mt * 16 + r;
            int col = wn * 16 + nt * 8 + 2 * c4;
            *(float2*)(Pz + (size_t)row * N + col) =
                make_float2(acc[mt][nt][0], acc[mt][nt][1]);
            *(float2*)(Pz + (size_t)(row + 8) * N + col) =
                make_float2(acc[mt][nt][2], acc[mt][nt][3]);
        }
    }
}

// red2: dst = act(p0 + p1 + bias), float4-vectorized.
template <bool RELU>
__global__ __launch_bounds__(256) void red2(
    const float* __restrict__ p, int partStride,
    const float* __restrict__ bias,
    float* __restrict__ dst, int ncols, int total4)
{
    int i = blockIdx.x * 256 + threadIdx.x;
    if (i >= total4) return;
    float4 a = *(const float4*)(p + (size_t)i * 4);
    float4 b = *(const float4*)(p + partStride + (size_t)i * 4);
    int col = (i * 4) & (ncols - 1);
    float4 bb = *(const float4*)(bias + col);
    float4 o;
    o.x = a.x + b.x + bb.x;
    o.y = a.y + b.y + bb.y;
    o.z = a.z + b.z + bb.z;
    o.w = a.w + b.w + bb.w;
    if (RELU) {
        o.x = fmaxf(o.x, 0.f); o.y = fmaxf(o.y, 0.f);
        o.z = fmaxf(o.z, 0.f); o.w = fmaxf(o.w, 0.f);
    }
    *(float4*)(dst + (size_t)i * 4) = o;
}

// ---------------------------------------------------------------------------
// launch
// ---------------------------------------------------------------------------
extern "C" void kernel_launch(void* const* d_in, const int* in_sizes, int n_in,
                              void* d_out, int out_size)
{
    const float* x   = (const float*)d_in[0];
    const float* Wk  = (const float*)d_in[1];
    const float* bk  = (const float*)d_in[2];
    const float* Wq  = (const float*)d_in[3];
    const float* bq  = (const float*)d_in[4];
    const float* Wv  = (const float*)d_in[5];
    const float* bv  = (const float*)d_in[6];
    const float* Wa1 = (const float*)d_in[7];
    const float* ba1 = (const float*)d_in[8];
    const float* Wa2 = (const float*)d_in[9];
    const float* ba2 = (const float*)d_in[10];
    const float* Wd1 = (const float*)d_in[11];
    const float* bd1 = (const float*)d_in[12];
    const float* Wd2 = (const float*)d_in[13];
    const float* bd2 = (const float*)d_in[14];
    float* out = (float*)d_out;

    float *pWall, *pball, *phkq, *pw, *pc, *ph1, *ppart, *ppd;
    cudaGetSymbolAddress((void**)&pWall, g_Wall);
    cudaGetSymbolAddress((void**)&pball, g_ball);
    cudaGetSymbolAddress((void**)&phkq, g_hkq);
    cudaGetSymbolAddress((void**)&pw,   g_w);
    cudaGetSymbolAddress((void**)&pc,   g_c);
    cudaGetSymbolAddress((void**)&ph1,  g_h1);
    cudaGetSymbolAddress((void**)&ppart, g_part);
    cudaGetSymbolAddress((void**)&ppd,  g_pd);

    cudaFuncSetAttribute((const void*)gemm_qkv,
                         cudaFuncAttributeMaxDynamicSharedMemorySize, GEMM_SMEM_SPLIT);
    cudaFuncSetAttribute((const void*)wv_gemm,
                         cudaFuncAttributeMaxDynamicSharedMemorySize, GEMM_SMEM_WV);
    cudaFuncSetAttribute((const void*)gemm_part,
                         cudaFuncAttributeMaxDynamicSharedMemorySize, GEMM_SMEM_1X);

    // 1. fused effective weights + biases
    prep_kernel<<<32, 256>>>(Wk, bk, Wq, bq, Wv, bv, Wa1, ba1);

    // 2. [hk|hq|v] = x @ Wall + ball   (2-pass: exact A)
    gemm_qkv<<<dim3(6, 32), 256, GEMM_SMEM_SPLIT>>>(
        x, 128, pWall, 384, pball, phkq, 256, pc, 640, 256, 128);

    // 3. attention scores (dots fused) -> g_w in mma-fragment layout
    score_kernel<<<dim3(4, 32, 8), 256>>>(phkq, pw, Wa2, ba2);

    // 4. o = w @ v, split-K=4, full-N tile -> partials, then reduce
    wv_gemm<<<dim3(16, 32), 256, GEMM_SMEM_WV>>>(pw, pc, ppart);
    wv_reduce<<<1024, 256>>>(ppart, pc);

    // 5. h1 = relu(c @ Wd1 + bd1), split-K=2 (Kper=320) + reduce
    gemm_part<<<dim3(4, 32, 2), 256, GEMM_SMEM_1X>>>(
        pc, 640, Wd1, 256, ppd, 256, 320, 2048 * 256);
    red2<true><<<512, 256>>>(ppd, 2048 * 256, bd1, ph1, 256, 131072);

    // 6. out = h1 @ Wd2 + bd2, split-K=2 (Kper=128) + reduce
    gemm_part<<<dim3(2, 32, 2), 256, GEMM_SMEM_1X>>>(
        ph1, 256, Wd2, 128, ppd, 128, 128, 2048 * 128);
    red2<false><<<256, 256>>>(ppd, 2048 * 128, bd2, out, 128, 65536);
}